// round 6
// baseline (speedup 1.0000x reference)
#include <cuda_runtime.h>
#include <cuda_fp16.h>
#include <cstdint>

#define NB    2048
#define TT    128
#define FF    64
#define HH    256
#define OUTL  32
#define BT    16
#define NCTA  (NB / BT)
#define NTHR  1024
#define ROWP  20

// Packed weights, 2 k-rows per entry: [k2][j]
__device__ float4 g_eP4[(FF / 2) * HH];   // (r_k, z_k, r_k1, z_k1) for Wih
__device__ float2 g_eN2[(FF / 2) * HH];
__device__ float4 g_hP4[(HH / 2) * HH];   // Whh
__device__ float2 g_hN2[(HH / 2) * HH];
__device__ float4 g_dP4[(HH / 2) * HH];   // dWhh
__device__ float2 g_dN2[(HH / 2) * HH];
__device__ float2 g_W12[(HH / 2) * HH];   // f1W
// Encoder hidden states: fp32 (A/C pass) + fp16 (ctx stream)
__device__ float  g_hsf[(size_t)NB * TT * HH];
__device__ __half g_hs [(size_t)NB * TT * HH];

typedef unsigned long long u64;

__device__ __forceinline__ u64 fma2(u64 a, u64 b, u64 c) {
    u64 d;
    asm("fma.rn.f32x2 %0, %1, %2, %3;" : "=l"(d) : "l"(a), "l"(b), "l"(c));
    return d;
}
__device__ __forceinline__ u64 dup2(float w) {
    unsigned r = __float_as_uint(w);
    u64 d;
    asm("mov.b64 %0, {%1, %1};" : "=l"(d) : "r"(r));
    return d;
}
__device__ __forceinline__ float2 unpk(u64 a) {
    unsigned lo, hi;
    asm("mov.b64 {%0, %1}, %2;" : "=r"(lo), "=r"(hi) : "l"(a));
    return make_float2(__uint_as_float(lo), __uint_as_float(hi));
}
__device__ __forceinline__ float sigf(float x) {
    return __fdividef(1.f, 1.f + __expf(-x));
}
__device__ __forceinline__ float tanh_f(float x) {
    return 2.f * sigf(2.f * x) - 1.f;
}

__global__ void prep_kernel(const float* __restrict__ eWih, const float* __restrict__ eWhh,
                            const float* __restrict__ dWhh, const float* __restrict__ f1W) {
    int i = blockIdx.x * blockDim.x + threadIdx.x;
    if (i >= (HH / 2) * HH) return;
    int k2 = i >> 8, j = i & 255;
    int k = 2 * k2;
    g_hP4[i] = make_float4(eWhh[(size_t)j * HH + k],       eWhh[(size_t)(j + HH) * HH + k],
                           eWhh[(size_t)j * HH + k + 1],   eWhh[(size_t)(j + HH) * HH + k + 1]);
    g_hN2[i] = make_float2(eWhh[(size_t)(j + 2 * HH) * HH + k],
                           eWhh[(size_t)(j + 2 * HH) * HH + k + 1]);
    g_dP4[i] = make_float4(dWhh[(size_t)j * HH + k],       dWhh[(size_t)(j + HH) * HH + k],
                           dWhh[(size_t)j * HH + k + 1],   dWhh[(size_t)(j + HH) * HH + k + 1]);
    g_dN2[i] = make_float2(dWhh[(size_t)(j + 2 * HH) * HH + k],
                           dWhh[(size_t)(j + 2 * HH) * HH + k + 1]);
    g_W12[i] = make_float2(f1W[(size_t)j * HH + k], f1W[(size_t)j * HH + k + 1]);
    if (k2 < FF / 2) {
        g_eP4[k2 * HH + j] = make_float4(
            eWih[(size_t)j * FF + k],     eWih[(size_t)(j + HH) * FF + k],
            eWih[(size_t)j * FF + k + 1], eWih[(size_t)(j + HH) * FF + k + 1]);
        g_eN2[k2 * HH + j] = make_float2(
            eWih[(size_t)(j + 2 * HH) * FF + k], eWih[(size_t)(j + 2 * HH) * FF + k + 1]);
    }
}

struct SM {
    float hti[2][HH][ROWP];   // transposed h tiles [k][b]; decoder: [1]=ctx, [0]=hd
    float xti[2][FF][ROWP];   // double-buffered transposed x tile
    float A[BT][TT];
    float C[BT][TT];
    float ww[BT][TT];
    float ctxp[8][BT][HH];    // ctx partials [t-eighth][b][c]
    float wpart[32][4];
    float prevs[BT];
};

__global__ void __launch_bounds__(NTHR, 1)
forecaster_kernel(
    const float* __restrict__ x,     const float* __restrict__ h0,
    const float* __restrict__ ebih,  const float* __restrict__ ebhh,
    const float* __restrict__ dWih,  const float* __restrict__ dbih,
    const float* __restrict__ dbhh,  const float* __restrict__ aWq,
    const float* __restrict__ abq,   const float* __restrict__ f1b,
    const float* __restrict__ f2W,   const float* __restrict__ f2b,
    float* __restrict__ out)
{
    extern __shared__ char smraw[];
    SM* sm = (SM*)smraw;
    const int tid  = threadIdx.x, wid = tid >> 5, lane = tid & 31;
    const int j     = tid & 255;
    const int bh    = tid >> 8;          // 0..3
    const int bbase = bh * 4;            // 4 owned batch rows
    const int b0    = blockIdx.x * BT;

    float hreg[4];
    #pragma unroll
    for (int bb = 0; bb < 4; bb++) {
        float v = h0[(size_t)(b0 + bbase + bb) * HH + j];
        hreg[bb] = v;
        sm->hti[0][j][bbase + bb] = v;
    }
    {   // stage x for t=0 (1 float per thread)
        int b = tid >> 6, k = tid & 63;
        sm->xti[0][k][b] = x[(size_t)(b0 + b) * TT * FF + k];
    }
    const float ebR  = ebih[j]          + ebhh[j];
    const float ebZ  = ebih[j + HH]     + ebhh[j + HH];
    const float ebNi = ebih[j + 2 * HH];
    const float ebNh = ebhh[j + 2 * HH];

    // ======================= ENCODER =======================
    int cur = 0;
    for (int t = 0; t < TT; t++) {
        __syncthreads();
        {   // stage x for t+1 into the other buffer
            int tn = (t + 1 < TT) ? t + 1 : t;
            int b = tid >> 6, k = tid & 63;
            sm->xti[(t + 1) & 1][k][b] = x[((size_t)(b0 + b) * TT + tn) * FF + k];
        }

        u64 aR[2], aZ[2], aN[2];
        #pragma unroll
        for (int p = 0; p < 2; p++) { aR[p] = 0; aZ[p] = 0; aN[p] = 0; }

        // gi = x_t @ Wih^T
        const float4* eP = g_eP4 + j;
        const float2* eN = g_eN2 + j;
        const float  (*xcur)[ROWP] = sm->xti[t & 1];
        #pragma unroll 2
        for (int k2 = 0; k2 < FF / 2; k2++) {
            float4 w4 = eP[k2 * HH];
            float2 n2 = eN[k2 * HH];
            u64 wr0 = dup2(w4.x), wz0 = dup2(w4.y), wn0 = dup2(n2.x);
            u64 wr1 = dup2(w4.z), wz1 = dup2(w4.w), wn1 = dup2(n2.y);
            ulonglong2 hv0 = *(const ulonglong2*)&xcur[2 * k2][bbase];
            ulonglong2 hv1 = *(const ulonglong2*)&xcur[2 * k2 + 1][bbase];
            aR[0] = fma2(wr0, hv0.x, aR[0]); aR[0] = fma2(wr1, hv1.x, aR[0]);
            aZ[0] = fma2(wz0, hv0.x, aZ[0]); aZ[0] = fma2(wz1, hv1.x, aZ[0]);
            aN[0] = fma2(wn0, hv0.x, aN[0]); aN[0] = fma2(wn1, hv1.x, aN[0]);
            aR[1] = fma2(wr0, hv0.y, aR[1]); aR[1] = fma2(wr1, hv1.y, aR[1]);
            aZ[1] = fma2(wz0, hv0.y, aZ[1]); aZ[1] = fma2(wz1, hv1.y, aZ[1]);
            aN[1] = fma2(wn0, hv0.y, aN[1]); aN[1] = fma2(wn1, hv1.y, aN[1]);
        }
        u64 ni[2];
        #pragma unroll
        for (int p = 0; p < 2; p++) { ni[p] = aN[p]; aN[p] = 0; }

        // gh = h @ Whh^T
        const float4* hP = g_hP4 + j;
        const float2* hN = g_hN2 + j;
        const float  (*hcur)[ROWP] = sm->hti[cur];
        #pragma unroll 2
        for (int k2 = 0; k2 < HH / 2; k2++) {
            float4 w4 = hP[k2 * HH];
            float2 n2 = hN[k2 * HH];
            u64 wr0 = dup2(w4.x), wz0 = dup2(w4.y), wn0 = dup2(n2.x);
            u64 wr1 = dup2(w4.z), wz1 = dup2(w4.w), wn1 = dup2(n2.y);
            ulonglong2 hv0 = *(const ulonglong2*)&hcur[2 * k2][bbase];
            ulonglong2 hv1 = *(const ulonglong2*)&hcur[2 * k2 + 1][bbase];
            aR[0] = fma2(wr0, hv0.x, aR[0]); aR[0] = fma2(wr1, hv1.x, aR[0]);
            aZ[0] = fma2(wz0, hv0.x, aZ[0]); aZ[0] = fma2(wz1, hv1.x, aZ[0]);
            aN[0] = fma2(wn0, hv0.x, aN[0]); aN[0] = fma2(wn1, hv1.x, aN[0]);
            aR[1] = fma2(wr0, hv0.y, aR[1]); aR[1] = fma2(wr1, hv1.y, aR[1]);
            aZ[1] = fma2(wz0, hv0.y, aZ[1]); aZ[1] = fma2(wz1, hv1.y, aZ[1]);
            aN[1] = fma2(wn0, hv0.y, aN[1]); aN[1] = fma2(wn1, hv1.y, aN[1]);
        }

        const int nxt = cur ^ 1;
        #pragma unroll
        for (int p = 0; p < 2; p++) {
            float2 r2 = unpk(aR[p]), z2 = unpk(aZ[p]);
            float2 nh2 = unpk(aN[p]), ni2 = unpk(ni[p]);
            {
                float r = sigf(r2.x + ebR), z = sigf(z2.x + ebZ);
                float n = tanh_f(ni2.x + ebNi + r * (nh2.x + ebNh));
                hreg[2 * p] = (1.f - z) * n + z * hreg[2 * p];
            }
            {
                float r = sigf(r2.y + ebR), z = sigf(z2.y + ebZ);
                float n = tanh_f(ni2.y + ebNi + r * (nh2.y + ebNh));
                hreg[2 * p + 1] = (1.f - z) * n + z * hreg[2 * p + 1];
            }
        }
        *(float4*)&sm->hti[nxt][j][bbase] =
            make_float4(hreg[0], hreg[1], hreg[2], hreg[3]);
        #pragma unroll
        for (int bb = 0; bb < 4; bb++) {
            size_t off = ((size_t)(b0 + bbase + bb) * TT + t) * HH + j;
            g_hsf[off] = hreg[bb];
            g_hs[off]  = __float2half(hreg[bb]);
        }
        cur = nxt;
    }
    __syncthreads();

    // ---- A/C pass: A[b][t]=Wq.h, C[b][t]=bq.h from fp32 scratch ----
    {
        int b = wid & 15;           // warp per (batch row, t-half)
        int thalf = wid >> 4;
        float wq[8], bq[8];
        {
            float4 a0 = *(const float4*)&aWq[lane * 8];
            float4 a1 = *(const float4*)&aWq[lane * 8 + 4];
            float4 c0 = *(const float4*)&abq[lane * 8];
            float4 c1 = *(const float4*)&abq[lane * 8 + 4];
            wq[0]=a0.x; wq[1]=a0.y; wq[2]=a0.z; wq[3]=a0.w;
            wq[4]=a1.x; wq[5]=a1.y; wq[6]=a1.z; wq[7]=a1.w;
            bq[0]=c0.x; bq[1]=c0.y; bq[2]=c0.z; bq[3]=c0.w;
            bq[4]=c1.x; bq[5]=c1.y; bq[6]=c1.z; bq[7]=c1.w;
        }
        const float* hb = g_hsf + (size_t)(b0 + b) * TT * HH + lane * 8;
        for (int ti = 0; ti < TT / 2; ti++) {
            int t = thalf * (TT / 2) + ti;
            float4 h0v = *(const float4*)(hb + (size_t)t * HH);
            float4 h1v = *(const float4*)(hb + (size_t)t * HH + 4);
            float pa = wq[0]*h0v.x + wq[1]*h0v.y + wq[2]*h0v.z + wq[3]*h0v.w
                     + wq[4]*h1v.x + wq[5]*h1v.y + wq[6]*h1v.z + wq[7]*h1v.w;
            float pc = bq[0]*h0v.x + bq[1]*h0v.y + bq[2]*h0v.z + bq[3]*h0v.w
                     + bq[4]*h1v.x + bq[5]*h1v.y + bq[6]*h1v.z + bq[7]*h1v.w;
            #pragma unroll
            for (int off = 16; off; off >>= 1) {
                pa += __shfl_xor_sync(0xffffffffu, pa, off);
                pc += __shfl_xor_sync(0xffffffffu, pc, off);
            }
            if (lane == 0) { sm->A[b][t] = pa; sm->C[b][t] = pc; }
        }
    }

    // ======================= DECODER =======================
    const float dbR  = dbih[j]          + dbhh[j];
    const float dbZ  = dbih[j + HH]     + dbhh[j + HH];
    const float dbNi = dbih[j + 2 * HH];
    const float dbNh = dbhh[j + 2 * HH];
    const float wiR  = dWih[j];
    const float wiZ  = dWih[j + HH];
    const float wiN  = dWih[j + 2 * HH];
    const float f2w  = f2W[j];
    const float f1bv = f1b[j];
    const float f2b0 = f2b[0];

    if (tid < BT)
        sm->prevs[tid] = x[((size_t)(b0 + tid) * TT + (TT - 1)) * FF];
    __syncthreads();

    const float scale = 0.0625f;
    for (int s = 0; s < OUTL; s++) {
        // scores + softmax: warps 0..15, one per batch row
        if (wid < BT) {
            int b = wid;
            float p = sm->prevs[b];
            float sc[4]; float mx = -1e30f;
            #pragma unroll
            for (int i = 0; i < 4; i++) {
                int tt2 = lane + 32 * i;
                sc[i] = (p * sm->A[b][tt2] + sm->C[b][tt2]) * scale;
                mx = fmaxf(mx, sc[i]);
            }
            #pragma unroll
            for (int off = 16; off; off >>= 1)
                mx = fmaxf(mx, __shfl_xor_sync(0xffffffffu, mx, off));
            float sum = 0.f;
            #pragma unroll
            for (int i = 0; i < 4; i++) { sc[i] = __expf(sc[i] - mx); sum += sc[i]; }
            #pragma unroll
            for (int off = 16; off; off >>= 1)
                sum += __shfl_xor_sync(0xffffffffu, sum, off);
            float inv = __fdividef(1.f, sum);
            #pragma unroll
            for (int i = 0; i < 4; i++) sm->ww[b][lane + 32 * i] = sc[i] * inv;
        }
        __syncthreads();

        // ctx = sum_t w[t]*hs[t] over 8 t-eighths (fp16 stream)
        {
            int th = tid >> 7, c = (tid & 127) * 2;
            float2 acc[BT];
            #pragma unroll
            for (int b = 0; b < BT; b++) acc[b] = make_float2(0.f, 0.f);
            const __half* base = g_hs + ((size_t)b0 * TT + th * 16) * HH + c;
            #pragma unroll 1
            for (int ti = 0; ti < 16; ti++) {
                int tt2 = th * 16 + ti;
                const __half* pb = base + (size_t)ti * HH;
                #pragma unroll
                for (int b = 0; b < BT; b++) {
                    float wv = sm->ww[b][tt2];
                    __half2 hv = *(const __half2*)(pb + (size_t)b * TT * HH);
                    float2 f = __half22float2(hv);
                    acc[b].x = fmaf(wv, f.x, acc[b].x);
                    acc[b].y = fmaf(wv, f.y, acc[b].y);
                }
            }
            #pragma unroll
            for (int b = 0; b < BT; b++)
                *(float2*)&sm->ctxp[th][b][c] = acc[b];
        }
        __syncthreads();
        {   // combine eighths into transposed ctx tile hti[1][k][b]
            #pragma unroll
            for (int bb = 0; bb < 4; bb++) {
                int b = bbase + bb;
                float v = 0.f;
                #pragma unroll
                for (int q = 0; q < 8; q++) v += sm->ctxp[q][b][j];
                sm->hti[1][j][b] = v;
            }
        }
        __syncthreads();

        // decoder GRU: gh = ctx @ dWhh^T (packed)
        {
            u64 aR[2], aZ[2], aN[2];
            #pragma unroll
            for (int p = 0; p < 2; p++) { aR[p] = 0; aZ[p] = 0; aN[p] = 0; }
            const float4* dP = g_dP4 + j;
            const float2* dN = g_dN2 + j;
            const float (*ccur)[ROWP] = sm->hti[1];
            #pragma unroll 2
            for (int k2 = 0; k2 < HH / 2; k2++) {
                float4 w4 = dP[k2 * HH];
                float2 n2 = dN[k2 * HH];
                u64 wr0 = dup2(w4.x), wz0 = dup2(w4.y), wn0 = dup2(n2.x);
                u64 wr1 = dup2(w4.z), wz1 = dup2(w4.w), wn1 = dup2(n2.y);
                ulonglong2 hv0 = *(const ulonglong2*)&ccur[2 * k2][bbase];
                ulonglong2 hv1 = *(const ulonglong2*)&ccur[2 * k2 + 1][bbase];
                aR[0] = fma2(wr0, hv0.x, aR[0]); aR[0] = fma2(wr1, hv1.x, aR[0]);
                aZ[0] = fma2(wz0, hv0.x, aZ[0]); aZ[0] = fma2(wz1, hv1.x, aZ[0]);
                aN[0] = fma2(wn0, hv0.x, aN[0]); aN[0] = fma2(wn1, hv1.x, aN[0]);
                aR[1] = fma2(wr0, hv0.y, aR[1]); aR[1] = fma2(wr1, hv1.y, aR[1]);
                aZ[1] = fma2(wz0, hv0.y, aZ[1]); aZ[1] = fma2(wz1, hv1.y, aZ[1]);
                aN[1] = fma2(wn0, hv0.y, aN[1]); aN[1] = fma2(wn1, hv1.y, aN[1]);
            }
            float hdv[4];
            #pragma unroll
            for (int p = 0; p < 2; p++) {
                float2 r2 = unpk(aR[p]), z2 = unpk(aZ[p]), nh2 = unpk(aN[p]);
                {
                    int bb = 2 * p; float pv = sm->prevs[bbase + bb];
                    float r = sigf(r2.x + pv * wiR + dbR);
                    float z = sigf(z2.x + pv * wiZ + dbZ);
                    float n = tanh_f(pv * wiN + dbNi + r * (nh2.x + dbNh));
                    hdv[bb] = (1.f - z) * n + z * sm->hti[1][j][bbase + bb];
                }
                {
                    int bb = 2 * p + 1; float pv = sm->prevs[bbase + bb];
                    float r = sigf(r2.y + pv * wiR + dbR);
                    float z = sigf(z2.y + pv * wiZ + dbZ);
                    float n = tanh_f(pv * wiN + dbNi + r * (nh2.y + dbNh));
                    hdv[bb] = (1.f - z) * n + z * sm->hti[1][j][bbase + bb];
                }
            }
            __syncthreads();
            *(float4*)&sm->hti[0][j][bbase] =
                make_float4(hdv[0], hdv[1], hdv[2], hdv[3]);
        }
        __syncthreads();

        // fc1(relu) + fc2 (packed f1W)
        {
            u64 aF[2];
            aF[0] = 0; aF[1] = 0;
            const float2* w1 = g_W12 + j;
            const float (*hdc)[ROWP] = sm->hti[0];
            #pragma unroll 2
            for (int k2 = 0; k2 < HH / 2; k2++) {
                float2 w2 = w1[k2 * HH];
                u64 wa = dup2(w2.x), wb = dup2(w2.y);
                ulonglong2 hv0 = *(const ulonglong2*)&hdc[2 * k2][bbase];
                ulonglong2 hv1 = *(const ulonglong2*)&hdc[2 * k2 + 1][bbase];
                aF[0] = fma2(wa, hv0.x, aF[0]); aF[0] = fma2(wb, hv1.x, aF[0]);
                aF[1] = fma2(wa, hv0.y, aF[1]); aF[1] = fma2(wb, hv1.y, aF[1]);
            }
            float2 f0 = unpk(aF[0]), f1 = unpk(aF[1]);
            float v[4];
            v[0] = fmaxf(f0.x + f1bv, 0.f) * f2w;
            v[1] = fmaxf(f0.y + f1bv, 0.f) * f2w;
            v[2] = fmaxf(f1.x + f1bv, 0.f) * f2w;
            v[3] = fmaxf(f1.y + f1bv, 0.f) * f2w;
            #pragma unroll
            for (int p = 0; p < 4; p++) {
                #pragma unroll
                for (int off = 16; off; off >>= 1)
                    v[p] += __shfl_down_sync(0xffffffffu, v[p], off);
            }
            if (lane == 0) {
                sm->wpart[wid][0] = v[0];
                sm->wpart[wid][1] = v[1];
                sm->wpart[wid][2] = v[2];
                sm->wpart[wid][3] = v[3];
            }
        }
        __syncthreads();
        if (tid < BT) {
            float o = f2b0;
            int wb = (tid >> 2) * 8;   // warps covering this batch group (bh = tid>>2)
            #pragma unroll
            for (int w = 0; w < 8; w++) o += sm->wpart[wb + w][tid & 3];
            out[(size_t)(b0 + tid) * OUTL + s] = o;
            sm->prevs[tid] = o;
        }
        __syncthreads();
    }
}

extern "C" void kernel_launch(void* const* d_in, const int* in_sizes, int n_in,
                              void* d_out, int out_size) {
    const float* x    = (const float*)d_in[0];
    const float* h0   = (const float*)d_in[1];
    const float* eWih = (const float*)d_in[2];
    const float* eWhh = (const float*)d_in[3];
    const float* ebih = (const float*)d_in[4];
    const float* ebhh = (const float*)d_in[5];
    const float* dWih = (const float*)d_in[6];
    const float* dWhh = (const float*)d_in[7];
    const float* dbih = (const float*)d_in[8];
    const float* dbhh = (const float*)d_in[9];
    const float* aWq  = (const float*)d_in[10];
    const float* abq  = (const float*)d_in[11];
    const float* f1W  = (const float*)d_in[12];
    const float* f1b  = (const float*)d_in[13];
    const float* f2W  = (const float*)d_in[14];
    const float* f2b  = (const float*)d_in[15];
    float* out = (float*)d_out;

    prep_kernel<<<((HH / 2) * HH + 255) / 256, 256>>>(eWih, eWhh, dWhh, f1W);

    size_t shmem = sizeof(SM);
    cudaFuncSetAttribute(forecaster_kernel,
                         cudaFuncAttributeMaxDynamicSharedMemorySize, (int)shmem);
    forecaster_kernel<<<NCTA, NTHR, shmem>>>(
        x, h0, ebih, ebhh, dWih, dbih, dbhh, aWq, abq, f1b, f2W, f2b, out);
}

// round 8
// speedup vs baseline: 2.5389x; 2.5389x over previous
#include <cuda_runtime.h>
#include <cuda_fp16.h>
#include <cuda_bf16.h>
#include <cstdint>

#define NB    2048
#define TT    128
#define FF    64
#define HH    256
#define OUTL  32
#define BT    16
#define NCTA  (NB / BT)
#define NTHR  512
#define ROWP  20
#define NKT   20          // k-tiles of 16 over K=320
#define AROW  344         // padded bf16 elems per A row (odd multiple of 16 -> conflict-free LDSM)
#define NJOBS 120         // 20 kt * 6 jobs

// Encoder weights as pre-swizzled mma B fragments (hi/lo bf16): [w][job][lane][4 u32]
__device__ unsigned g_Bfrag[16 * NJOBS * 32 * 4];
// Decoder packed weights
__device__ float4 g_dP4[(HH / 2) * HH];
__device__ float2 g_dN2[(HH / 2) * HH];
__device__ float2 g_W12[(HH / 2) * HH];
// Encoder hidden states: fp32 (A/C pass) + fp16 (ctx stream)
__device__ float  g_hsf[(size_t)NB * TT * HH];
__device__ __half g_hs [(size_t)NB * TT * HH];

typedef unsigned long long u64;

__device__ __forceinline__ float sigf(float x) {
    return __fdividef(1.f, 1.f + __expf(-x));
}
__device__ __forceinline__ float tanh_f(float x) {
    return 2.f * sigf(2.f * x) - 1.f;
}
__device__ __forceinline__ unsigned packhi(float a, float b) {
    __nv_bfloat16 ha = __float2bfloat16(a), hb = __float2bfloat16(b);
    return (unsigned)__bfloat16_as_ushort(ha) |
           ((unsigned)__bfloat16_as_ushort(hb) << 16);
}
__device__ __forceinline__ unsigned packlo(float a, float b) {
    __nv_bfloat16 ha = __float2bfloat16(a), hb = __float2bfloat16(b);
    __nv_bfloat16 la = __float2bfloat16(a - __bfloat162float(ha));
    __nv_bfloat16 lb = __float2bfloat16(b - __bfloat162float(hb));
    return (unsigned)__bfloat16_as_ushort(la) |
           ((unsigned)__bfloat16_as_ushort(lb) << 16);
}
__device__ __forceinline__ u64 fma2(u64 a, u64 b, u64 c) {
    u64 d;
    asm("fma.rn.f32x2 %0, %1, %2, %3;" : "=l"(d) : "l"(a), "l"(b), "l"(c));
    return d;
}
__device__ __forceinline__ u64 dup2(float w) {
    unsigned r = __float_as_uint(w);
    u64 d;
    asm("mov.b64 %0, {%1, %1};" : "=l"(d) : "r"(r));
    return d;
}
__device__ __forceinline__ float2 unpk(u64 a) {
    unsigned lo, hi;
    asm("mov.b64 {%0, %1}, %2;" : "=r"(lo), "=r"(hi) : "l"(a));
    return make_float2(__uint_as_float(lo), __uint_as_float(hi));
}

#define MMA(cc, a0, a1, a2, a3, bb0, bb1)                                      \
    asm volatile(                                                              \
        "mma.sync.aligned.m16n8k16.row.col.f32.bf16.bf16.f32 "                 \
        "{%0,%1,%2,%3},{%4,%5,%6,%7},{%8,%9},{%0,%1,%2,%3};"                   \
        : "+f"(cc[0]), "+f"(cc[1]), "+f"(cc[2]), "+f"(cc[3])                   \
        : "r"(a0), "r"(a1), "r"(a2), "r"(a3), "r"(bb0), "r"(bb1))

#define MMA3(cc, bv)                                                           \
    do {                                                                       \
        MMA(cc, ah0, ah1, ah2, ah3, bv.x, bv.y);                               \
        MMA(cc, al0, al1, al2, al3, bv.x, bv.y);                               \
        MMA(cc, ah0, ah1, ah2, ah3, bv.z, bv.w);                               \
    } while (0)

#define LDSM4(r0, r1, r2, r3, addr)                                            \
    asm volatile("ldmatrix.sync.aligned.m8n8.x4.shared.b16 {%0,%1,%2,%3}, [%4];" \
                 : "=r"(r0), "=r"(r1), "=r"(r2), "=r"(r3) : "r"(addr))

// ---- prep: encoder weight fragments ----
__device__ __forceinline__ float fetchW(const float* eWih, const float* eWhh,
                                        int g, int j, int k) {
    if (g == 0) return k < FF ? eWih[(size_t)j * FF + k] : eWhh[(size_t)j * HH + (k - FF)];
    if (g == 1) return k < FF ? eWih[(size_t)(j + HH) * FF + k]
                              : eWhh[(size_t)(j + HH) * HH + (k - FF)];
    if (g == 2) return k >= FF ? eWhh[(size_t)(j + 2 * HH) * HH + (k - FF)] : 0.f;
    return k < FF ? eWih[(size_t)(j + 2 * HH) * FF + k] : 0.f;
}

__global__ void prep_frag(const float* __restrict__ eWih, const float* __restrict__ eWhh) {
    int idx = blockIdx.x * blockDim.x + threadIdx.x;
    if (idx >= 16 * NJOBS * 32) return;
    int lane = idx & 31;
    int job  = (idx >> 5) % NJOBS;
    int w    = idx / (NJOBS * 32);
    int kt = job / 6, sub = job % 6;
    int g, ct;
    if (sub < 4) { g = sub >> 1; ct = sub & 1; }
    else         { g = (kt < 4) ? 3 : 2; ct = sub - 4; }
    int j  = 16 * w + ct * 8 + (lane >> 2);
    int k0 = kt * 16 + (lane & 3) * 2;
    float w00 = fetchW(eWih, eWhh, g, j, k0);
    float w01 = fetchW(eWih, eWhh, g, j, k0 + 1);
    float w10 = fetchW(eWih, eWhh, g, j, k0 + 8);
    float w11 = fetchW(eWih, eWhh, g, j, k0 + 9);
    unsigned* o = g_Bfrag + (size_t)idx * 4;
    o[0] = packhi(w00, w01);
    o[1] = packhi(w10, w11);
    o[2] = packlo(w00, w01);
    o[3] = packlo(w10, w11);
}

__global__ void prep_dec(const float* __restrict__ dWhh, const float* __restrict__ f1W) {
    int i = blockIdx.x * blockDim.x + threadIdx.x;
    if (i >= (HH / 2) * HH) return;
    int k2 = i >> 8, jj = i & 255;
    int k = 2 * k2;
    g_dP4[i] = make_float4(dWhh[(size_t)jj * HH + k],       dWhh[(size_t)(jj + HH) * HH + k],
                           dWhh[(size_t)jj * HH + k + 1],   dWhh[(size_t)(jj + HH) * HH + k + 1]);
    g_dN2[i] = make_float2(dWhh[(size_t)(jj + 2 * HH) * HH + k],
                           dWhh[(size_t)(jj + 2 * HH) * HH + k + 1]);
    g_W12[i] = make_float2(f1W[(size_t)jj * HH + k], f1W[(size_t)jj * HH + k + 1]);
}

struct SM {
    unsigned short abfH[BT][AROW];   // A operand hi bf16: rows=batch, cols=k (x | h)
    unsigned short abfL[BT][AROW];   // lo residual
    float hti[2][HH][ROWP];          // decoder: [1]=ctx, [0]=hd (transposed [k][b])
    float A[BT][TT];
    float C[BT][TT];
    float ww[BT][TT];
    float ctxp[4][BT][HH];
    float wpart[16][8];
    float prevs[BT];
};

__global__ void __launch_bounds__(NTHR, 1)
forecaster_kernel(
    const float* __restrict__ x,     const float* __restrict__ h0,
    const float* __restrict__ ebih,  const float* __restrict__ ebhh,
    const float* __restrict__ dWih,  const float* __restrict__ dbih,
    const float* __restrict__ dbhh,  const float* __restrict__ aWq,
    const float* __restrict__ abq,   const float* __restrict__ f1b,
    const float* __restrict__ f2W,   const float* __restrict__ f2b,
    float* __restrict__ out)
{
    extern __shared__ char smraw[];
    SM* sm = (SM*)smraw;
    const int tid = threadIdx.x, wid = tid >> 5, lane = tid & 31;
    const int b0 = blockIdx.x * BT;

    // ================= ENCODER (mma) =================
    const int r0l = lane >> 2;              // local batch row (0..7); +8 for second
    const int jc  = (lane & 3) * 2;
    const int jA  = 16 * wid + jc;          // ct=0 unit pair
    const int jB  = jA + 8;                 // ct=1 unit pair

    // per-thread gate biases for the 2x2 owned units
    float bR[2][2], bZ[2][2], bNi[2][2], bNh[2][2];
    #pragma unroll
    for (int ct = 0; ct < 2; ct++) {
        int jj = ct ? jB : jA;
        #pragma unroll
        for (int q = 0; q < 2; q++) {
            bR[ct][q]  = ebih[jj + q]          + ebhh[jj + q];
            bZ[ct][q]  = ebih[jj + q + HH]     + ebhh[jj + q + HH];
            bNi[ct][q] = ebih[jj + q + 2 * HH];
            bNh[ct][q] = ebhh[jj + q + 2 * HH];
        }
    }
    // h_prev in registers, positions match C fragment layout
    float hp[2][4];
    #pragma unroll
    for (int ct = 0; ct < 2; ct++) {
        int jj = ct ? jB : jA;
        #pragma unroll
        for (int pos = 0; pos < 4; pos++) {
            int b = r0l + ((pos >> 1) ? 8 : 0);
            hp[ct][pos] = h0[(size_t)(b0 + b) * HH + jj + (pos & 1)];
        }
    }
    // initial A smem: h part
    #pragma unroll
    for (int ct = 0; ct < 2; ct++) {
        int jj = ct ? jB : jA;
        #pragma unroll
        for (int br = 0; br < 2; br++) {
            int b = r0l + br * 8;
            float v0 = hp[ct][br * 2 + 0], v1 = hp[ct][br * 2 + 1];
            *(unsigned*)&sm->abfH[b][FF + jj] = packhi(v0, v1);
            *(unsigned*)&sm->abfL[b][FF + jj] = packlo(v0, v1);
        }
    }
    // initial x stage (t=0)
    {
        int i0 = tid * 2, bx = i0 >> 6, kx = i0 & 63;
        float2 xv = *(const float2*)&x[(size_t)(b0 + bx) * TT * FF + kx];
        *(unsigned*)&sm->abfH[bx][kx] = packhi(xv.x, xv.y);
        *(unsigned*)&sm->abfL[bx][kx] = packlo(xv.x, xv.y);
    }
    // per-lane ldmatrix row base addresses
    const unsigned aH = (unsigned)__cvta_generic_to_shared(&sm->abfH[0][0])
                      + (lane & 15) * (AROW * 2) + ((lane >> 4) * 8) * 2;
    const unsigned aL = (unsigned)__cvta_generic_to_shared(&sm->abfL[0][0])
                      + (lane & 15) * (AROW * 2) + ((lane >> 4) * 8) * 2;
    __syncthreads();

    for (int t = 0; t < TT; t++) {
        float c0t[4] = {0, 0, 0, 0}, c1t[4] = {0, 0, 0, 0};
        float c2t[4] = {0, 0, 0, 0}, c3t[4] = {0, 0, 0, 0};
        float c4t[4] = {0, 0, 0, 0}, c5t[4] = {0, 0, 0, 0};
        float c6t[4] = {0, 0, 0, 0}, c7t[4] = {0, 0, 0, 0};

        #pragma unroll 2
        for (int kt = 0; kt < NKT; kt++) {
            unsigned ah0, ah1, ah2, ah3, al0, al1, al2, al3;
            LDSM4(ah0, ah1, ah2, ah3, aH + kt * 32);
            LDSM4(al0, al1, al2, al3, aL + kt * 32);
            const uint4* bp = reinterpret_cast<const uint4*>(
                g_Bfrag + ((size_t)(wid * NJOBS + kt * 6) * 32 + lane) * 4);
            uint4 bv;
            bv = bp[0];       MMA3(c0t, bv);
            bv = bp[32];      MMA3(c1t, bv);
            bv = bp[64];      MMA3(c2t, bv);
            bv = bp[96];      MMA3(c3t, bv);
            if (kt < 4) {
                bv = bp[128]; MMA3(c6t, bv);
                bv = bp[160]; MMA3(c7t, bv);
            } else {
                bv = bp[128]; MMA3(c4t, bv);
                bv = bp[160]; MMA3(c5t, bv);
            }
        }
        __syncthreads();   // all warps done reading A smem

        // epilogue: gates + recurrence, all warp-local
        #pragma unroll
        for (int ct = 0; ct < 2; ct++) {
            int jj = ct ? jB : jA;
            const float* cr = ct ? c1t : c0t;
            const float* cz = ct ? c3t : c2t;
            const float* ch = ct ? c5t : c4t;
            const float* ci = ct ? c7t : c6t;
            #pragma unroll
            for (int br = 0; br < 2; br++) {
                int b = r0l + br * 8;
                float hn[2];
                #pragma unroll
                for (int q = 0; q < 2; q++) {
                    int pos = br * 2 + q;
                    float rr = sigf(cr[pos] + bR[ct][q]);
                    float zz = sigf(cz[pos] + bZ[ct][q]);
                    float nn = tanh_f(ci[pos] + bNi[ct][q] + rr * (ch[pos] + bNh[ct][q]));
                    hn[q] = (1.f - zz) * nn + zz * hp[ct][pos];
                    hp[ct][pos] = hn[q];
                }
                *(unsigned*)&sm->abfH[b][FF + jj] = packhi(hn[0], hn[1]);
                *(unsigned*)&sm->abfL[b][FF + jj] = packlo(hn[0], hn[1]);
                size_t go = ((size_t)(b0 + b) * TT + t) * HH + jj;
                *(float2*)&g_hsf[go] = make_float2(hn[0], hn[1]);
                *(__half2*)&g_hs[go] = __floats2half2_rn(hn[0], hn[1]);
            }
        }
        // stage x for t+1
        if (t + 1 < TT) {
            int i0 = tid * 2, bx = i0 >> 6, kx = i0 & 63;
            float2 xv = *(const float2*)&x[((size_t)(b0 + bx) * TT + (t + 1)) * FF + kx];
            *(unsigned*)&sm->abfH[bx][kx] = packhi(xv.x, xv.y);
            *(unsigned*)&sm->abfL[bx][kx] = packlo(xv.x, xv.y);
        }
        __syncthreads();
    }

    // ---- A/C pass: A[b][t]=Wq.h, C[b][t]=bq.h from fp32 scratch ----
    {
        int b = wid;   // warp per batch row
        float wq[8], bq[8];
        {
            float4 a0 = *(const float4*)&aWq[lane * 8];
            float4 a1 = *(const float4*)&aWq[lane * 8 + 4];
            float4 cc0 = *(const float4*)&abq[lane * 8];
            float4 cc1 = *(const float4*)&abq[lane * 8 + 4];
            wq[0]=a0.x; wq[1]=a0.y; wq[2]=a0.z; wq[3]=a0.w;
            wq[4]=a1.x; wq[5]=a1.y; wq[6]=a1.z; wq[7]=a1.w;
            bq[0]=cc0.x; bq[1]=cc0.y; bq[2]=cc0.z; bq[3]=cc0.w;
            bq[4]=cc1.x; bq[5]=cc1.y; bq[6]=cc1.z; bq[7]=cc1.w;
        }
        const float* hb = g_hsf + (size_t)(b0 + b) * TT * HH + lane * 8;
        for (int t = 0; t < TT; t++) {
            float4 h0v = *(const float4*)(hb + (size_t)t * HH);
            float4 h1v = *(const float4*)(hb + (size_t)t * HH + 4);
            float pa = wq[0]*h0v.x + wq[1]*h0v.y + wq[2]*h0v.z + wq[3]*h0v.w
                     + wq[4]*h1v.x + wq[5]*h1v.y + wq[6]*h1v.z + wq[7]*h1v.w;
            float pc = bq[0]*h0v.x + bq[1]*h0v.y + bq[2]*h0v.z + bq[3]*h0v.w
                     + bq[4]*h1v.x + bq[5]*h1v.y + bq[6]*h1v.z + bq[7]*h1v.w;
            #pragma unroll
            for (int off = 16; off; off >>= 1) {
                pa += __shfl_xor_sync(0xffffffffu, pa, off);
                pc += __shfl_xor_sync(0xffffffffu, pc, off);
            }
            if (lane == 0) { sm->A[b][t] = pa; sm->C[b][t] = pc; }
        }
    }

    // ======================= DECODER (FFMA2, as R4) =======================
    const int jd    = tid & 255;
    const int bhd   = tid >> 8;
    const int bbase = bhd * 8;

    const float dbR  = dbih[jd]          + dbhh[jd];
    const float dbZ  = dbih[jd + HH]     + dbhh[jd + HH];
    const float dbNi = dbih[jd + 2 * HH];
    const float dbNh = dbhh[jd + 2 * HH];
    const float wiR  = dWih[jd];
    const float wiZ  = dWih[jd + HH];
    const float wiN  = dWih[jd + 2 * HH];
    const float f2w  = f2W[jd];
    const float f1bv = f1b[jd];
    const float f2b0 = f2b[0];

    if (tid < BT)
        sm->prevs[tid] = x[((size_t)(b0 + tid) * TT + (TT - 1)) * FF];
    __syncthreads();

    const float scale = 0.0625f;
    for (int s = 0; s < OUTL; s++) {
        // scores + softmax: warp wid handles batch row b=wid
        {
            int b = wid;
            float p = sm->prevs[b];
            float sc[4]; float mx = -1e30f;
            #pragma unroll
            for (int i = 0; i < 4; i++) {
                int tt2 = lane + 32 * i;
                sc[i] = (p * sm->A[b][tt2] + sm->C[b][tt2]) * scale;
                mx = fmaxf(mx, sc[i]);
            }
            #pragma unroll
            for (int off = 16; off; off >>= 1)
                mx = fmaxf(mx, __shfl_xor_sync(0xffffffffu, mx, off));
            float sum = 0.f;
            #pragma unroll
            for (int i = 0; i < 4; i++) { sc[i] = __expf(sc[i] - mx); sum += sc[i]; }
            #pragma unroll
            for (int off = 16; off; off >>= 1)
                sum += __shfl_xor_sync(0xffffffffu, sum, off);
            float inv = __fdividef(1.f, sum);
            #pragma unroll
            for (int i = 0; i < 4; i++) sm->ww[b][lane + 32 * i] = sc[i] * inv;
        }
        __syncthreads();

        // ctx = sum_t w[t]*hs[t] over 4 t-quarters (fp16 stream)
        {
            int th = tid >> 7, c = (tid & 127) * 2;
            float2 acc[BT];
            #pragma unroll
            for (int b = 0; b < BT; b++) acc[b] = make_float2(0.f, 0.f);
            const __half* base = g_hs + ((size_t)b0 * TT + th * 32) * HH + c;
            #pragma unroll 1
            for (int ti = 0; ti < 32; ti++) {
                int tt2 = th * 32 + ti;
                const __half* pb = base + (size_t)ti * HH;
                #pragma unroll
                for (int b = 0; b < BT; b++) {
                    float wv = sm->ww[b][tt2];
                    __half2 hv = *(const __half2*)(pb + (size_t)b * TT * HH);
                    float2 f = __half22float2(hv);
                    acc[b].x = fmaf(wv, f.x, acc[b].x);
                    acc[b].y = fmaf(wv, f.y, acc[b].y);
                }
            }
            #pragma unroll
            for (int b = 0; b < BT; b++)
                *(float2*)&sm->ctxp[th][b][c] = acc[b];
        }
        __syncthreads();
        {
            #pragma unroll
            for (int bb = 0; bb < 8; bb++) {
                int b = bbase + bb;
                sm->hti[1][jd][b] = sm->ctxp[0][b][jd] + sm->ctxp[1][b][jd]
                                  + sm->ctxp[2][b][jd] + sm->ctxp[3][b][jd];
            }
        }
        __syncthreads();

        // decoder GRU: gh = ctx @ dWhh^T (packed FFMA2)
        {
            u64 aR[4], aZ[4], aN[4];
            #pragma unroll
            for (int p = 0; p < 4; p++) { aR[p] = 0; aZ[p] = 0; aN[p] = 0; }
            const float4* dP = g_dP4 + jd;
            const float2* dN = g_dN2 + jd;
            const float (*ccur)[ROWP] = sm->hti[1];
            #pragma unroll 4
            for (int k2 = 0; k2 < HH / 2; k2++) {
                float4 w4 = dP[k2 * HH];
                float2 n2 = dN[k2 * HH];
                u64 wr0 = dup2(w4.x), wz0 = dup2(w4.y), wn0 = dup2(n2.x);
                u64 wr1 = dup2(w4.z), wz1 = dup2(w4.w), wn1 = dup2(n2.y);
                ulonglong2 h0a = *(const ulonglong2*)&ccur[2 * k2][bbase];
                ulonglong2 h0b = *(const ulonglong2*)&ccur[2 * k2][bbase + 4];
                ulonglong2 h1a = *(const ulonglong2*)&ccur[2 * k2 + 1][bbase];
                ulonglong2 h1b = *(const ulonglong2*)&ccur[2 * k2 + 1][bbase + 4];
                aR[0] = fma2(wr0, h0a.x, aR[0]); aR[0] = fma2(wr1, h1a.x, aR[0]);
                aZ[0] = fma2(wz0, h0a.x, aZ[0]); aZ[0] = fma2(wz1, h1a.x, aZ[0]);
                aN[0] = fma2(wn0, h0a.x, aN[0]); aN[0] = fma2(wn1, h1a.x, aN[0]);
                aR[1] = fma2(wr0, h0a.y, aR[1]); aR[1] = fma2(wr1, h1a.y, aR[1]);
                aZ[1] = fma2(wz0, h0a.y, aZ[1]); aZ[1] = fma2(wz1, h1a.y, aZ[1]);
                aN[1] = fma2(wn0, h0a.y, aN[1]); aN[1] = fma2(wn1, h1a.y, aN[1]);
                aR[2] = fma2(wr0, h0b.x, aR[2]); aR[2] = fma2(wr1, h1b.x, aR[2]);
                aZ[2] = fma2(wz0, h0b.x, aZ[2]); aZ[2] = fma2(wz1, h1b.x, aZ[2]);
                aN[2] = fma2(wn0, h0b.x, aN[2]); aN[2] = fma2(wn1, h1b.x, aN[2]);
                aR[3] = fma2(wr0, h0b.y, aR[3]); aR[3] = fma2(wr1, h1b.y, aR[3]);
                aZ[3] = fma2(wz0, h0b.y, aZ[3]); aZ[3] = fma2(wz1, h1b.y, aZ[3]);
                aN[3] = fma2(wn0, h0b.y, aN[3]); aN[3] = fma2(wn1, h1b.y, aN[3]);
            }
            float hdv[8];
            #pragma unroll
            for (int p = 0; p < 4; p++) {
                float2 r2 = unpk(aR[p]), z2 = unpk(aZ[p]), nh2 = unpk(aN[p]);
                {
                    int bb = 2 * p; float pv = sm->prevs[bbase + bb];
                    float r = sigf(r2.x + pv * wiR + dbR);
                    float z = sigf(z2.x + pv * wiZ + dbZ);
                    float n = tanh_f(pv * wiN + dbNi + r * (nh2.x + dbNh));
                    hdv[bb] = (1.f - z) * n + z * sm->hti[1][jd][bbase + bb];
                }
                {
                    int bb = 2 * p + 1; float pv = sm->prevs[bbase + bb];
                    float r = sigf(r2.y + pv * wiR + dbR);
                    float z = sigf(z2.y + pv * wiZ + dbZ);
                    float n = tanh_f(pv * wiN + dbNi + r * (nh2.y + dbNh));
                    hdv[bb] = (1.f - z) * n + z * sm->hti[1][jd][bbase + bb];
                }
            }
            __syncthreads();
            *(float4*)&sm->hti[0][jd][bbase] =
                make_float4(hdv[0], hdv[1], hdv[2], hdv[3]);
            *(float4*)&sm->hti[0][jd][bbase + 4] =
                make_float4(hdv[4], hdv[5], hdv[6], hdv[7]);
        }
        __syncthreads();

        // fc1(relu) + fc2
        {
            u64 aF[4];
            #pragma unroll
            for (int p = 0; p < 4; p++) aF[p] = 0;
            const float2* w1 = g_W12 + jd;
            const float (*hdc)[ROWP] = sm->hti[0];
            #pragma unroll 4
            for (int k2 = 0; k2 < HH / 2; k2++) {
                float2 w2 = w1[k2 * HH];
                u64 wa = dup2(w2.x), wb = dup2(w2.y);
                ulonglong2 h0a = *(const ulonglong2*)&hdc[2 * k2][bbase];
                ulonglong2 h0b = *(const ulonglong2*)&hdc[2 * k2][bbase + 4];
                ulonglong2 h1a = *(const ulonglong2*)&hdc[2 * k2 + 1][bbase];
                ulonglong2 h1b = *(const ulonglong2*)&hdc[2 * k2 + 1][bbase + 4];
                aF[0] = fma2(wa, h0a.x, aF[0]); aF[0] = fma2(wb, h1a.x, aF[0]);
                aF[1] = fma2(wa, h0a.y, aF[1]); aF[1] = fma2(wb, h1a.y, aF[1]);
                aF[2] = fma2(wa, h0b.x, aF[2]); aF[2] = fma2(wb, h1b.x, aF[2]);
                aF[3] = fma2(wa, h0b.y, aF[3]); aF[3] = fma2(wb, h1b.y, aF[3]);
            }
            #pragma unroll
            for (int p = 0; p < 4; p++) {
                float2 f = unpk(aF[p]);
                float v0 = fmaxf(f.x + f1bv, 0.f) * f2w;
                float v1 = fmaxf(f.y + f1bv, 0.f) * f2w;
                #pragma unroll
                for (int off = 16; off; off >>= 1) {
                    v0 += __shfl_down_sync(0xffffffffu, v0, off);
                    v1 += __shfl_down_sync(0xffffffffu, v1, off);
                }
                if (lane == 0) {
                    sm->wpart[wid][2 * p]     = v0;
                    sm->wpart[wid][2 * p + 1] = v1;
                }
            }
        }
        __syncthreads();
        if (tid < BT) {
            float o = f2b0;
            int wb = (tid >> 3) * 8;
            #pragma unroll
            for (int w = 0; w < 8; w++) o += sm->wpart[wb + w][tid & 7];
            out[(size_t)(b0 + tid) * OUTL + s] = o;
            sm->prevs[tid] = o;
        }
        __syncthreads();
    }
}

extern "C" void kernel_launch(void* const* d_in, const int* in_sizes, int n_in,
                              void* d_out, int out_size) {
    const float* x    = (const float*)d_in[0];
    const float* h0   = (const float*)d_in[1];
    const float* eWih = (const float*)d_in[2];
    const float* eWhh = (const float*)d_in[3];
    const float* ebih = (const float*)d_in[4];
    const float* ebhh = (const float*)d_in[5];
    const float* dWih = (const float*)d_in[6];
    const float* dWhh = (const float*)d_in[7];
    const float* dbih = (const float*)d_in[8];
    const float* dbhh = (const float*)d_in[9];
    const float* aWq  = (const float*)d_in[10];
    const float* abq  = (const float*)d_in[11];
    const float* f1W  = (const float*)d_in[12];
    const float* f1b  = (const float*)d_in[13];
    const float* f2W  = (const float*)d_in[14];
    const float* f2b  = (const float*)d_in[15];
    float* out = (float*)d_out;

    prep_frag<<<(16 * NJOBS * 32 + 255) / 256, 256>>>(eWih, eWhh);
    prep_dec<<<((HH / 2) * HH + 255) / 256, 256>>>(dWhh, f1W);

    size_t shmem = sizeof(SM);
    cudaFuncSetAttribute(forecaster_kernel,
                         cudaFuncAttributeMaxDynamicSharedMemorySize, (int)shmem);
    forecaster_kernel<<<NCTA, NTHR, shmem>>>(
        x, h0, ebih, ebhh, dWih, dbih, dbhh, aWq, abq, f1b, f2W, f2b, out);
}

// round 9
// speedup vs baseline: 3.3388x; 1.3151x over previous
#include <cuda_runtime.h>
#include <cuda_fp16.h>
#include <cuda_bf16.h>
#include <cstdint>

#define NB    2048
#define TT    128
#define FF    64
#define HH    256
#define OUTL  32
#define BT    16
#define NCTA  (NB / BT)
#define NTHR  512
#define ROWP  20
#define NKT   20          // encoder k-tiles of 16 over K=320
#define AROW  344         // padded bf16 elems per A row (odd multiple of 16 -> conflict-free LDSM)
#define NJOBS 120         // encoder: 20 kt * 6 jobs
#define DJOBS 96          // decoder GRU: 16 kt * 6 jobs
#define FJOBS 32          // fc1: 16 kt * 2 jobs

// Pre-swizzled mma B fragments (hi/lo bf16): [w][job][lane][4 u32]
__device__ unsigned g_Bfrag [16 * NJOBS * 32 * 4];   // encoder
__device__ unsigned g_BfragD[16 * DJOBS * 32 * 4];   // decoder GRU (dWhh)
__device__ unsigned g_BfragF[16 * FJOBS * 32 * 4];   // fc1
// Encoder hidden states: fp32 (A/C pass) + fp16 (ctx stream)
__device__ float  g_hsf[(size_t)NB * TT * HH];
__device__ __half g_hs [(size_t)NB * TT * HH];

__device__ __forceinline__ float sigf(float x) {
    return __fdividef(1.f, 1.f + __expf(-x));
}
__device__ __forceinline__ float tanh_f(float x) {
    return 2.f * sigf(2.f * x) - 1.f;
}
__device__ __forceinline__ unsigned packhi(float a, float b) {
    __nv_bfloat16 ha = __float2bfloat16(a), hb = __float2bfloat16(b);
    return (unsigned)__bfloat16_as_ushort(ha) |
           ((unsigned)__bfloat16_as_ushort(hb) << 16);
}
__device__ __forceinline__ unsigned packlo(float a, float b) {
    __nv_bfloat16 ha = __float2bfloat16(a), hb = __float2bfloat16(b);
    __nv_bfloat16 la = __float2bfloat16(a - __bfloat162float(ha));
    __nv_bfloat16 lb = __float2bfloat16(b - __bfloat162float(hb));
    return (unsigned)__bfloat16_as_ushort(la) |
           ((unsigned)__bfloat16_as_ushort(lb) << 16);
}

#define MMA(cc, a0, a1, a2, a3, bb0, bb1)                                      \
    asm volatile(                                                              \
        "mma.sync.aligned.m16n8k16.row.col.f32.bf16.bf16.f32 "                 \
        "{%0,%1,%2,%3},{%4,%5,%6,%7},{%8,%9},{%0,%1,%2,%3};"                   \
        : "+f"(cc[0]), "+f"(cc[1]), "+f"(cc[2]), "+f"(cc[3])                   \
        : "r"(a0), "r"(a1), "r"(a2), "r"(a3), "r"(bb0), "r"(bb1))

#define MMA3(cc, bv)                                                           \
    do {                                                                       \
        MMA(cc, ah0, ah1, ah2, ah3, bv.x, bv.y);                               \
        MMA(cc, al0, al1, al2, al3, bv.x, bv.y);                               \
        MMA(cc, ah0, ah1, ah2, ah3, bv.z, bv.w);                               \
    } while (0)

#define LDSM4(r0, r1, r2, r3, addr)                                            \
    asm volatile("ldmatrix.sync.aligned.m8n8.x4.shared.b16 {%0,%1,%2,%3}, [%4];" \
                 : "=r"(r0), "=r"(r1), "=r"(r2), "=r"(r3) : "r"(addr))

// ---- prep: encoder weight fragments ----
__device__ __forceinline__ float fetchW(const float* eWih, const float* eWhh,
                                        int g, int j, int k) {
    if (g == 0) return k < FF ? eWih[(size_t)j * FF + k] : eWhh[(size_t)j * HH + (k - FF)];
    if (g == 1) return k < FF ? eWih[(size_t)(j + HH) * FF + k]
                              : eWhh[(size_t)(j + HH) * HH + (k - FF)];
    if (g == 2) return k >= FF ? eWhh[(size_t)(j + 2 * HH) * HH + (k - FF)] : 0.f;
    return k < FF ? eWih[(size_t)(j + 2 * HH) * FF + k] : 0.f;
}

__global__ void prep_frag(const float* __restrict__ eWih, const float* __restrict__ eWhh) {
    int idx = blockIdx.x * blockDim.x + threadIdx.x;
    if (idx >= 16 * NJOBS * 32) return;
    int lane = idx & 31;
    int job  = (idx >> 5) % NJOBS;
    int w    = idx / (NJOBS * 32);
    int kt = job / 6, sub = job % 6;
    int g, ct;
    if (sub < 4) { g = sub >> 1; ct = sub & 1; }
    else         { g = (kt < 4) ? 3 : 2; ct = sub - 4; }
    int j  = 16 * w + ct * 8 + (lane >> 2);
    int k0 = kt * 16 + (lane & 3) * 2;
    float w00 = fetchW(eWih, eWhh, g, j, k0);
    float w01 = fetchW(eWih, eWhh, g, j, k0 + 1);
    float w10 = fetchW(eWih, eWhh, g, j, k0 + 8);
    float w11 = fetchW(eWih, eWhh, g, j, k0 + 9);
    unsigned* o = g_Bfrag + (size_t)idx * 4;
    o[0] = packhi(w00, w01);
    o[1] = packhi(w10, w11);
    o[2] = packlo(w00, w01);
    o[3] = packlo(w10, w11);
}

// decoder GRU fragments: jobs = kt(0..15)*6 + sub; sub: g=sub>>1 (r,z,n), ct=sub&1
__global__ void prep_fragD(const float* __restrict__ dWhh) {
    int idx = blockIdx.x * blockDim.x + threadIdx.x;
    if (idx >= 16 * DJOBS * 32) return;
    int lane = idx & 31;
    int job  = (idx >> 5) % DJOBS;
    int w    = idx / (DJOBS * 32);
    int kt = job / 6, sub = job % 6;
    int g = sub >> 1, ct = sub & 1;
    int j  = 16 * w + ct * 8 + (lane >> 2);
    int k0 = kt * 16 + (lane & 3) * 2;
    const float* row = dWhh + (size_t)(j + g * HH) * HH;
    float w00 = row[k0],     w01 = row[k0 + 1];
    float w10 = row[k0 + 8], w11 = row[k0 + 9];
    unsigned* o = g_BfragD + (size_t)idx * 4;
    o[0] = packhi(w00, w01);
    o[1] = packhi(w10, w11);
    o[2] = packlo(w00, w01);
    o[3] = packlo(w10, w11);
}

// fc1 fragments: jobs = kt(0..15)*2 + ct
__global__ void prep_fragF(const float* __restrict__ f1W) {
    int idx = blockIdx.x * blockDim.x + threadIdx.x;
    if (idx >= 16 * FJOBS * 32) return;
    int lane = idx & 31;
    int job  = (idx >> 5) % FJOBS;
    int w    = idx / (FJOBS * 32);
    int kt = job >> 1, ct = job & 1;
    int j  = 16 * w + ct * 8 + (lane >> 2);
    int k0 = kt * 16 + (lane & 3) * 2;
    const float* row = f1W + (size_t)j * HH;
    float w00 = row[k0],     w01 = row[k0 + 1];
    float w10 = row[k0 + 8], w11 = row[k0 + 9];
    unsigned* o = g_BfragF + (size_t)idx * 4;
    o[0] = packhi(w00, w01);
    o[1] = packhi(w10, w11);
    o[2] = packlo(w00, w01);
    o[3] = packlo(w10, w11);
}

struct SM {
    unsigned short abfH[BT][AROW];   // A operand hi bf16 (enc: x|h; dec: -|ctx then -|hd)
    unsigned short abfL[BT][AROW];   // lo residual
    float ctxf[HH][ROWP];            // fp32 ctx, transposed [k][b] (for exact blend)
    float A[BT][TT];
    float C[BT][TT];
    float ww[BT][TT];
    float ctxp[4][BT][HH];
    float wpart[16][BT];
    float prevs[BT];
};

__global__ void __launch_bounds__(NTHR, 1)
forecaster_kernel(
    const float* __restrict__ x,     const float* __restrict__ h0,
    const float* __restrict__ ebih,  const float* __restrict__ ebhh,
    const float* __restrict__ dWih,  const float* __restrict__ dbih,
    const float* __restrict__ dbhh,  const float* __restrict__ aWq,
    const float* __restrict__ abq,   const float* __restrict__ f1b,
    const float* __restrict__ f2W,   const float* __restrict__ f2b,
    float* __restrict__ out)
{
    extern __shared__ char smraw[];
    SM* sm = (SM*)smraw;
    const int tid = threadIdx.x, wid = tid >> 5, lane = tid & 31;
    const int b0 = blockIdx.x * BT;

    const int r0l = lane >> 2;              // C-fragment local batch row (0..7)
    const int jc  = (lane & 3) * 2;
    const int jA  = 16 * wid + jc;          // ct=0 unit pair
    const int jB  = jA + 8;                 // ct=1 unit pair

    // ================= ENCODER (mma) =================
    float bR[2][2], bZ[2][2], bNi[2][2], bNh[2][2];
    #pragma unroll
    for (int ct = 0; ct < 2; ct++) {
        int jj = ct ? jB : jA;
        #pragma unroll
        for (int q = 0; q < 2; q++) {
            bR[ct][q]  = ebih[jj + q]          + ebhh[jj + q];
            bZ[ct][q]  = ebih[jj + q + HH]     + ebhh[jj + q + HH];
            bNi[ct][q] = ebih[jj + q + 2 * HH];
            bNh[ct][q] = ebhh[jj + q + 2 * HH];
        }
    }
    float hp[2][4];
    #pragma unroll
    for (int ct = 0; ct < 2; ct++) {
        int jj = ct ? jB : jA;
        #pragma unroll
        for (int pos = 0; pos < 4; pos++) {
            int b = r0l + ((pos >> 1) ? 8 : 0);
            hp[ct][pos] = h0[(size_t)(b0 + b) * HH + jj + (pos & 1)];
        }
    }
    #pragma unroll
    for (int ct = 0; ct < 2; ct++) {
        int jj = ct ? jB : jA;
        #pragma unroll
        for (int br = 0; br < 2; br++) {
            int b = r0l + br * 8;
            float v0 = hp[ct][br * 2 + 0], v1 = hp[ct][br * 2 + 1];
            *(unsigned*)&sm->abfH[b][FF + jj] = packhi(v0, v1);
            *(unsigned*)&sm->abfL[b][FF + jj] = packlo(v0, v1);
        }
    }
    {
        int i0 = tid * 2, bx = i0 >> 6, kx = i0 & 63;
        float2 xv = *(const float2*)&x[(size_t)(b0 + bx) * TT * FF + kx];
        *(unsigned*)&sm->abfH[bx][kx] = packhi(xv.x, xv.y);
        *(unsigned*)&sm->abfL[bx][kx] = packlo(xv.x, xv.y);
    }
    const unsigned aH = (unsigned)__cvta_generic_to_shared(&sm->abfH[0][0])
                      + (lane & 15) * (AROW * 2) + ((lane >> 4) * 8) * 2;
    const unsigned aL = (unsigned)__cvta_generic_to_shared(&sm->abfL[0][0])
                      + (lane & 15) * (AROW * 2) + ((lane >> 4) * 8) * 2;
    __syncthreads();

    for (int t = 0; t < TT; t++) {
        float c0t[4] = {0, 0, 0, 0}, c1t[4] = {0, 0, 0, 0};
        float c2t[4] = {0, 0, 0, 0}, c3t[4] = {0, 0, 0, 0};
        float c4t[4] = {0, 0, 0, 0}, c5t[4] = {0, 0, 0, 0};
        float c6t[4] = {0, 0, 0, 0}, c7t[4] = {0, 0, 0, 0};

        #pragma unroll 2
        for (int kt = 0; kt < NKT; kt++) {
            unsigned ah0, ah1, ah2, ah3, al0, al1, al2, al3;
            LDSM4(ah0, ah1, ah2, ah3, aH + kt * 32);
            LDSM4(al0, al1, al2, al3, aL + kt * 32);
            const uint4* bp = reinterpret_cast<const uint4*>(
                g_Bfrag + ((size_t)(wid * NJOBS + kt * 6) * 32 + lane) * 4);
            uint4 bv;
            bv = bp[0];       MMA3(c0t, bv);
            bv = bp[32];      MMA3(c1t, bv);
            bv = bp[64];      MMA3(c2t, bv);
            bv = bp[96];      MMA3(c3t, bv);
            if (kt < 4) {
                bv = bp[128]; MMA3(c6t, bv);
                bv = bp[160]; MMA3(c7t, bv);
            } else {
                bv = bp[128]; MMA3(c4t, bv);
                bv = bp[160]; MMA3(c5t, bv);
            }
        }
        __syncthreads();   // all warps done reading A smem

        #pragma unroll
        for (int ct = 0; ct < 2; ct++) {
            int jj = ct ? jB : jA;
            const float* cr = ct ? c1t : c0t;
            const float* cz = ct ? c3t : c2t;
            const float* ch = ct ? c5t : c4t;
            const float* ci = ct ? c7t : c6t;
            #pragma unroll
            for (int br = 0; br < 2; br++) {
                int b = r0l + br * 8;
                float hn[2];
                #pragma unroll
                for (int q = 0; q < 2; q++) {
                    int pos = br * 2 + q;
                    float rr = sigf(cr[pos] + bR[ct][q]);
                    float zz = sigf(cz[pos] + bZ[ct][q]);
                    float nn = tanh_f(ci[pos] + bNi[ct][q] + rr * (ch[pos] + bNh[ct][q]));
                    hn[q] = (1.f - zz) * nn + zz * hp[ct][pos];
                    hp[ct][pos] = hn[q];
                }
                *(unsigned*)&sm->abfH[b][FF + jj] = packhi(hn[0], hn[1]);
                *(unsigned*)&sm->abfL[b][FF + jj] = packlo(hn[0], hn[1]);
                size_t go = ((size_t)(b0 + b) * TT + t) * HH + jj;
                *(float2*)&g_hsf[go] = make_float2(hn[0], hn[1]);
                *(__half2*)&g_hs[go] = __floats2half2_rn(hn[0], hn[1]);
            }
        }
        if (t + 1 < TT) {
            int i0 = tid * 2, bx = i0 >> 6, kx = i0 & 63;
            float2 xv = *(const float2*)&x[((size_t)(b0 + bx) * TT + (t + 1)) * FF + kx];
            *(unsigned*)&sm->abfH[bx][kx] = packhi(xv.x, xv.y);
            *(unsigned*)&sm->abfL[bx][kx] = packlo(xv.x, xv.y);
        }
        __syncthreads();
    }

    // ---- A/C pass ----
    {
        int b = wid;
        float wq[8], bq[8];
        {
            float4 a0 = *(const float4*)&aWq[lane * 8];
            float4 a1 = *(const float4*)&aWq[lane * 8 + 4];
            float4 cc0 = *(const float4*)&abq[lane * 8];
            float4 cc1 = *(const float4*)&abq[lane * 8 + 4];
            wq[0]=a0.x; wq[1]=a0.y; wq[2]=a0.z; wq[3]=a0.w;
            wq[4]=a1.x; wq[5]=a1.y; wq[6]=a1.z; wq[7]=a1.w;
            bq[0]=cc0.x; bq[1]=cc0.y; bq[2]=cc0.z; bq[3]=cc0.w;
            bq[4]=cc1.x; bq[5]=cc1.y; bq[6]=cc1.z; bq[7]=cc1.w;
        }
        const float* hb = g_hsf + (size_t)(b0 + b) * TT * HH + lane * 8;
        for (int t = 0; t < TT; t++) {
            float4 h0v = *(const float4*)(hb + (size_t)t * HH);
            float4 h1v = *(const float4*)(hb + (size_t)t * HH + 4);
            float pa = wq[0]*h0v.x + wq[1]*h0v.y + wq[2]*h0v.z + wq[3]*h0v.w
                     + wq[4]*h1v.x + wq[5]*h1v.y + wq[6]*h1v.z + wq[7]*h1v.w;
            float pc = bq[0]*h0v.x + bq[1]*h0v.y + bq[2]*h0v.z + bq[3]*h0v.w
                     + bq[4]*h1v.x + bq[5]*h1v.y + bq[6]*h1v.z + bq[7]*h1v.w;
            #pragma unroll
            for (int off = 16; off; off >>= 1) {
                pa += __shfl_xor_sync(0xffffffffu, pa, off);
                pc += __shfl_xor_sync(0xffffffffu, pc, off);
            }
            if (lane == 0) { sm->A[b][t] = pa; sm->C[b][t] = pc; }
        }
    }

    // ======================= DECODER (mma) =======================
    // per-thread decoder constants for owned units
    float dR[2][2], dZ[2][2], dNi[2][2], dNh[2][2];
    float wiR[2][2], wiZ[2][2], wiN[2][2], f1bb[2][2], f2w[2][2];
    #pragma unroll
    for (int ct = 0; ct < 2; ct++) {
        int jj = ct ? jB : jA;
        #pragma unroll
        for (int q = 0; q < 2; q++) {
            dR[ct][q]   = dbih[jj + q]          + dbhh[jj + q];
            dZ[ct][q]   = dbih[jj + q + HH]     + dbhh[jj + q + HH];
            dNi[ct][q]  = dbih[jj + q + 2 * HH];
            dNh[ct][q]  = dbhh[jj + q + 2 * HH];
            wiR[ct][q]  = dWih[jj + q];
            wiZ[ct][q]  = dWih[jj + q + HH];
            wiN[ct][q]  = dWih[jj + q + 2 * HH];
            f1bb[ct][q] = f1b[jj + q];
            f2w[ct][q]  = f2W[jj + q];
        }
    }
    const float f2b0 = f2b[0];

    if (tid < BT)
        sm->prevs[tid] = x[((size_t)(b0 + tid) * TT + (TT - 1)) * FF];
    __syncthreads();

    const float scale = 0.0625f;
    for (int s = 0; s < OUTL; s++) {
        // ---- scores + softmax: warp per batch row ----
        {
            int b = wid;
            float p = sm->prevs[b];
            float sc[4]; float mx = -1e30f;
            #pragma unroll
            for (int i = 0; i < 4; i++) {
                int tt2 = lane + 32 * i;
                sc[i] = (p * sm->A[b][tt2] + sm->C[b][tt2]) * scale;
                mx = fmaxf(mx, sc[i]);
            }
            #pragma unroll
            for (int off = 16; off; off >>= 1)
                mx = fmaxf(mx, __shfl_xor_sync(0xffffffffu, mx, off));
            float sum = 0.f;
            #pragma unroll
            for (int i = 0; i < 4; i++) { sc[i] = __expf(sc[i] - mx); sum += sc[i]; }
            #pragma unroll
            for (int off = 16; off; off >>= 1)
                sum += __shfl_xor_sync(0xffffffffu, sum, off);
            float inv = __fdividef(1.f, sum);
            #pragma unroll
            for (int i = 0; i < 4; i++) sm->ww[b][lane + 32 * i] = sc[i] * inv;
        }
        __syncthreads();

        // ---- ctx partials over 4 t-quarters (fp16 stream) ----
        {
            int th = tid >> 7, c = (tid & 127) * 2;
            float2 acc[BT];
            #pragma unroll
            for (int b = 0; b < BT; b++) acc[b] = make_float2(0.f, 0.f);
            const __half* base = g_hs + ((size_t)b0 * TT + th * 32) * HH + c;
            #pragma unroll 1
            for (int ti = 0; ti < 32; ti++) {
                int tt2 = th * 32 + ti;
                const __half* pb = base + (size_t)ti * HH;
                #pragma unroll
                for (int b = 0; b < BT; b++) {
                    float wv = sm->ww[b][tt2];
                    __half2 hv = *(const __half2*)(pb + (size_t)b * TT * HH);
                    float2 f = __half22float2(hv);
                    acc[b].x = fmaf(wv, f.x, acc[b].x);
                    acc[b].y = fmaf(wv, f.y, acc[b].y);
                }
            }
            #pragma unroll
            for (int b = 0; b < BT; b++)
                *(float2*)&sm->ctxp[th][b][c] = acc[b];
        }
        __syncthreads();

        // ---- combine: fp32 ctx tile + bf16 hi/lo A tile ----
        {
            int jp = tid & 127, bq4 = tid >> 7;
            int j2 = jp * 2;
            #pragma unroll
            for (int bb = 0; bb < 4; bb++) {
                int b = bq4 * 4 + bb;
                float v0 = sm->ctxp[0][b][j2] + sm->ctxp[1][b][j2]
                         + sm->ctxp[2][b][j2] + sm->ctxp[3][b][j2];
                float v1 = sm->ctxp[0][b][j2 + 1] + sm->ctxp[1][b][j2 + 1]
                         + sm->ctxp[2][b][j2 + 1] + sm->ctxp[3][b][j2 + 1];
                sm->ctxf[j2][b]     = v0;
                sm->ctxf[j2 + 1][b] = v1;
                *(unsigned*)&sm->abfH[b][FF + j2] = packhi(v0, v1);
                *(unsigned*)&sm->abfL[b][FF + j2] = packlo(v0, v1);
            }
        }
        __syncthreads();

        // ---- decoder GRU mma: gh = ctx @ dWhh^T ----
        float cR0[4] = {0,0,0,0}, cR1[4] = {0,0,0,0};
        float cZ0[4] = {0,0,0,0}, cZ1[4] = {0,0,0,0};
        float cN0[4] = {0,0,0,0}, cN1[4] = {0,0,0,0};
        #pragma unroll 2
        for (int kt = 0; kt < 16; kt++) {
            unsigned ah0, ah1, ah2, ah3, al0, al1, al2, al3;
            LDSM4(ah0, ah1, ah2, ah3, aH + (kt + 4) * 32);
            LDSM4(al0, al1, al2, al3, aL + (kt + 4) * 32);
            const uint4* bp = reinterpret_cast<const uint4*>(
                g_BfragD + ((size_t)(wid * DJOBS + kt * 6) * 32 + lane) * 4);
            uint4 bv;
            bv = bp[0];   MMA3(cR0, bv);
            bv = bp[32];  MMA3(cR1, bv);
            bv = bp[64];  MMA3(cZ0, bv);
            bv = bp[96];  MMA3(cZ1, bv);
            bv = bp[128]; MMA3(cN0, bv);
            bv = bp[160]; MMA3(cN1, bv);
        }
        __syncthreads();   // all warps done reading ctx A tile

        // ---- GRU epilogue: hd -> abf tile (warp-local) ----
        #pragma unroll
        for (int ct = 0; ct < 2; ct++) {
            int jj = ct ? jB : jA;
            const float* cr = ct ? cR1 : cR0;
            const float* cz = ct ? cZ1 : cZ0;
            const float* cn = ct ? cN1 : cN0;
            #pragma unroll
            for (int br = 0; br < 2; br++) {
                int b = r0l + br * 8;
                float pv = sm->prevs[b];
                float hd[2];
                #pragma unroll
                for (int q = 0; q < 2; q++) {
                    int pos = br * 2 + q;
                    float rr = sigf(cr[pos] + pv * wiR[ct][q] + dR[ct][q]);
                    float zz = sigf(cz[pos] + pv * wiZ[ct][q] + dZ[ct][q]);
                    float nn = tanh_f(pv * wiN[ct][q] + dNi[ct][q]
                                      + rr * (cn[pos] + dNh[ct][q]));
                    float cx = sm->ctxf[jj + q][b];
                    hd[q] = (1.f - zz) * nn + zz * cx;
                }
                *(unsigned*)&sm->abfH[b][FF + jj] = packhi(hd[0], hd[1]);
                *(unsigned*)&sm->abfL[b][FF + jj] = packlo(hd[0], hd[1]);
            }
        }
        __syncthreads();

        // ---- fc1 mma + relu + fc2 reduce ----
        {
            float cF0[4] = {0,0,0,0}, cF1[4] = {0,0,0,0};
            #pragma unroll 2
            for (int kt = 0; kt < 16; kt++) {
                unsigned ah0, ah1, ah2, ah3, al0, al1, al2, al3;
                LDSM4(ah0, ah1, ah2, ah3, aH + (kt + 4) * 32);
                LDSM4(al0, al1, al2, al3, aL + (kt + 4) * 32);
                const uint4* bp = reinterpret_cast<const uint4*>(
                    g_BfragF + ((size_t)(wid * FJOBS + kt * 2) * 32 + lane) * 4);
                uint4 bv;
                bv = bp[0];  MMA3(cF0, bv);
                bv = bp[32]; MMA3(cF1, bv);
            }
            float s0 = 0.f, s1 = 0.f;
            #pragma unroll
            for (int ct = 0; ct < 2; ct++) {
                const float* cf = ct ? cF1 : cF0;
                #pragma unroll
                for (int q = 0; q < 2; q++) {
                    s0 += fmaxf(cf[q]     + f1bb[ct][q], 0.f) * f2w[ct][q];
                    s1 += fmaxf(cf[2 + q] + f1bb[ct][q], 0.f) * f2w[ct][q];
                }
            }
            s0 += __shfl_xor_sync(0xffffffffu, s0, 1);
            s0 += __shfl_xor_sync(0xffffffffu, s0, 2);
            s1 += __shfl_xor_sync(0xffffffffu, s1, 1);
            s1 += __shfl_xor_sync(0xffffffffu, s1, 2);
            if ((lane & 3) == 0) {
                sm->wpart[wid][r0l]     = s0;
                sm->wpart[wid][r0l + 8] = s1;
            }
        }
        __syncthreads();
        if (tid < BT) {
            float o = f2b0;
            #pragma unroll
            for (int w = 0; w < 16; w++) o += sm->wpart[w][tid];
            out[(size_t)(b0 + tid) * OUTL + s] = o;
            sm->prevs[tid] = o;
        }
        __syncthreads();
    }
}

extern "C" void kernel_launch(void* const* d_in, const int* in_sizes, int n_in,
                              void* d_out, int out_size) {
    const float* x    = (const float*)d_in[0];
    const float* h0   = (const float*)d_in[1];
    const float* eWih = (const float*)d_in[2];
    const float* eWhh = (const float*)d_in[3];
    const float* ebih = (const float*)d_in[4];
    const float* ebhh = (const float*)d_in[5];
    const float* dWih = (const float*)d_in[6];
    const float* dWhh = (const float*)d_in[7];
    const float* dbih = (const float*)d_in[8];
    const float* dbhh = (const float*)d_in[9];
    const float* aWq  = (const float*)d_in[10];
    const float* abq  = (const float*)d_in[11];
    const float* f1W  = (const float*)d_in[12];
    const float* f1b  = (const float*)d_in[13];
    const float* f2W  = (const float*)d_in[14];
    const float* f2b  = (const float*)d_in[15];
    float* out = (float*)d_out;

    prep_frag <<<(16 * NJOBS * 32 + 255) / 256, 256>>>(eWih, eWhh);
    prep_fragD<<<(16 * DJOBS * 32 + 255) / 256, 256>>>(dWhh);
    prep_fragF<<<(16 * FJOBS * 32 + 255) / 256, 256>>>(f1W);

    size_t shmem = sizeof(SM);
    cudaFuncSetAttribute(forecaster_kernel,
                         cudaFuncAttributeMaxDynamicSharedMemorySize, (int)shmem);
    forecaster_kernel<<<NCTA, NTHR, shmem>>>(
        x, h0, ebih, ebhh, dWih, dbih, dbhh, aWq, abq, f1b, f2W, f2b, out);
}

// round 11
// speedup vs baseline: 3.6979x; 1.1076x over previous
#include <cuda_runtime.h>
#include <cuda_fp16.h>
#include <cuda_bf16.h>
#include <cstdint>

#define NB    2048
#define TT    128
#define FF    64
#define HH    256
#define OUTL  32
#define BT    16
#define NCTA  (NB / BT)
#define NTHR  512
#define ROWP  20
#define NKT   20          // encoder k-tiles of 16 over K=320
#define AROW  344         // padded bf16 elems per A row
#define NJOBS 120         // encoder: 20 kt * 6 jobs
#define DJOBS 96          // decoder GRU: 16 kt * 6 jobs
#define FJOBS 32          // fc1: 16 kt * 2 jobs

// Pre-swizzled mma B fragments (hi/lo bf16): [w][job][lane][4 u32]
__device__ unsigned g_Bfrag [16 * NJOBS * 32 * 4];   // encoder
__device__ unsigned g_BfragD[16 * DJOBS * 32 * 4];   // decoder GRU (dWhh)
__device__ unsigned g_BfragF[16 * FJOBS * 32 * 4];   // fc1
// Encoder hidden states: fp32 (A/C pass) + fp16 (ctx stream)
__device__ float  g_hsf[(size_t)NB * TT * HH];
__device__ __half g_hs [(size_t)NB * TT * HH];

__device__ __forceinline__ float sigf(float x) {
    return __fdividef(1.f, 1.f + __expf(-x));
}
__device__ __forceinline__ float tanh_f(float x) {
    return 2.f * sigf(2.f * x) - 1.f;
}
__device__ __forceinline__ unsigned packhi(float a, float b) {
    __nv_bfloat16 ha = __float2bfloat16(a), hb = __float2bfloat16(b);
    return (unsigned)__bfloat16_as_ushort(ha) |
           ((unsigned)__bfloat16_as_ushort(hb) << 16);
}
__device__ __forceinline__ unsigned packlo(float a, float b) {
    __nv_bfloat16 ha = __float2bfloat16(a), hb = __float2bfloat16(b);
    __nv_bfloat16 la = __float2bfloat16(a - __bfloat162float(ha));
    __nv_bfloat16 lb = __float2bfloat16(b - __bfloat162float(hb));
    return (unsigned)__bfloat16_as_ushort(la) |
           ((unsigned)__bfloat16_as_ushort(lb) << 16);
}

#define MMA(cc, a0, a1, a2, a3, bb0, bb1)                                      \
    asm volatile(                                                              \
        "mma.sync.aligned.m16n8k16.row.col.f32.bf16.bf16.f32 "                 \
        "{%0,%1,%2,%3},{%4,%5,%6,%7},{%8,%9},{%0,%1,%2,%3};"                   \
        : "+f"(cc[0]), "+f"(cc[1]), "+f"(cc[2]), "+f"(cc[3])                   \
        : "r"(a0), "r"(a1), "r"(a2), "r"(a3), "r"(bb0), "r"(bb1))

#define MMA3(cc, bv)                                                           \
    do {                                                                       \
        MMA(cc, ah0, ah1, ah2, ah3, bv.x, bv.y);                               \
        MMA(cc, al0, al1, al2, al3, bv.x, bv.y);                               \
        MMA(cc, ah0, ah1, ah2, ah3, bv.z, bv.w);                               \
    } while (0)

#define LDSM4(r0, r1, r2, r3, addr)                                            \
    asm volatile("ldmatrix.sync.aligned.m8n8.x4.shared.b16 {%0,%1,%2,%3}, [%4];" \
                 : "=r"(r0), "=r"(r1), "=r"(r2), "=r"(r3) : "r"(addr))

#define CP16(dst, src)                                                         \
    asm volatile("cp.async.cg.shared.global [%0], [%1], 16;"                   \
                 :: "r"(dst), "l"(src))
#define CP_COMMIT() asm volatile("cp.async.commit_group;")
#define CP_WAIT1()  asm volatile("cp.async.wait_group 1;")
#define CP_WAIT0()  asm volatile("cp.async.wait_group 0;")

// ---- prep kernels ----
__device__ __forceinline__ float fetchW(const float* eWih, const float* eWhh,
                                        int g, int j, int k) {
    if (g == 0) return k < FF ? eWih[(size_t)j * FF + k] : eWhh[(size_t)j * HH + (k - FF)];
    if (g == 1) return k < FF ? eWih[(size_t)(j + HH) * FF + k]
                              : eWhh[(size_t)(j + HH) * HH + (k - FF)];
    if (g == 2) return k >= FF ? eWhh[(size_t)(j + 2 * HH) * HH + (k - FF)] : 0.f;
    return k < FF ? eWih[(size_t)(j + 2 * HH) * FF + k] : 0.f;
}

__global__ void prep_frag(const float* __restrict__ eWih, const float* __restrict__ eWhh) {
    int idx = blockIdx.x * blockDim.x + threadIdx.x;
    if (idx >= 16 * NJOBS * 32) return;
    int lane = idx & 31;
    int job  = (idx >> 5) % NJOBS;
    int w    = idx / (NJOBS * 32);
    int kt = job / 6, sub = job % 6;
    int g, ct;
    if (sub < 4) { g = sub >> 1; ct = sub & 1; }
    else         { g = (kt < 4) ? 3 : 2; ct = sub - 4; }
    int j  = 16 * w + ct * 8 + (lane >> 2);
    int k0 = kt * 16 + (lane & 3) * 2;
    float w00 = fetchW(eWih, eWhh, g, j, k0);
    float w01 = fetchW(eWih, eWhh, g, j, k0 + 1);
    float w10 = fetchW(eWih, eWhh, g, j, k0 + 8);
    float w11 = fetchW(eWih, eWhh, g, j, k0 + 9);
    unsigned* o = g_Bfrag + (size_t)idx * 4;
    o[0] = packhi(w00, w01);
    o[1] = packhi(w10, w11);
    o[2] = packlo(w00, w01);
    o[3] = packlo(w10, w11);
}

__global__ void prep_fragD(const float* __restrict__ dWhh) {
    int idx = blockIdx.x * blockDim.x + threadIdx.x;
    if (idx >= 16 * DJOBS * 32) return;
    int lane = idx & 31;
    int job  = (idx >> 5) % DJOBS;
    int w    = idx / (DJOBS * 32);
    int kt = job / 6, sub = job % 6;
    int g = sub >> 1, ct = sub & 1;
    int j  = 16 * w + ct * 8 + (lane >> 2);
    int k0 = kt * 16 + (lane & 3) * 2;
    const float* row = dWhh + (size_t)(j + g * HH) * HH;
    float w00 = row[k0],     w01 = row[k0 + 1];
    float w10 = row[k0 + 8], w11 = row[k0 + 9];
    unsigned* o = g_BfragD + (size_t)idx * 4;
    o[0] = packhi(w00, w01);
    o[1] = packhi(w10, w11);
    o[2] = packlo(w00, w01);
    o[3] = packlo(w10, w11);
}

__global__ void prep_fragF(const float* __restrict__ f1W) {
    int idx = blockIdx.x * blockDim.x + threadIdx.x;
    if (idx >= 16 * FJOBS * 32) return;
    int lane = idx & 31;
    int job  = (idx >> 5) % FJOBS;
    int w    = idx / (FJOBS * 32);
    int kt = job >> 1, ct = job & 1;
    int j  = 16 * w + ct * 8 + (lane >> 2);
    int k0 = kt * 16 + (lane & 3) * 2;
    const float* row = f1W + (size_t)j * HH;
    float w00 = row[k0],     w01 = row[k0 + 1];
    float w10 = row[k0 + 8], w11 = row[k0 + 9];
    unsigned* o = g_BfragF + (size_t)idx * 4;
    o[0] = packhi(w00, w01);
    o[1] = packhi(w10, w11);
    o[2] = packlo(w00, w01);
    o[3] = packlo(w10, w11);
}

struct SM {
    unsigned short abfH[BT][AROW];     // A operand hi bf16
    unsigned short abfL[BT][AROW];     // lo residual
    uint4 bstage[2][16][6][32];        // cp.async B staging (96 KB)
    float ctxf[HH][ROWP];              // fp32 ctx, transposed [k][b]
    float A[BT][TT];
    float C[BT][TT];
    float ww[BT][TT];
    __half2 ctxp[4][BT][HH / 2];       // ctx partials (fp16)
    float wpart[16][BT];
    float prevs[BT];
};

__global__ void __launch_bounds__(NTHR, 1)
forecaster_kernel(
    const float* __restrict__ x,     const float* __restrict__ h0,
    const float* __restrict__ ebih,  const float* __restrict__ ebhh,
    const float* __restrict__ dWih,  const float* __restrict__ dbih,
    const float* __restrict__ dbhh,  const float* __restrict__ aWq,
    const float* __restrict__ abq,   const float* __restrict__ f1b,
    const float* __restrict__ f2W,   const float* __restrict__ f2b,
    float* __restrict__ out)
{
    extern __shared__ char smraw[];
    SM* sm = (SM*)smraw;
    const int tid = threadIdx.x, wid = tid >> 5, lane = tid & 31;
    const int b0 = blockIdx.x * BT;

    const int r0l = lane >> 2;
    const int jc  = (lane & 3) * 2;
    const int jA  = 16 * wid + jc;
    const int jB  = jA + 8;

    // staging addresses (per warp, per buffer)
    unsigned stW[2];
    {
        unsigned base = (unsigned)__cvta_generic_to_shared(&sm->bstage[0][0][0][0]);
        stW[0] = base + ((0 * 16 + wid) * 6) * 32 * 16 + lane * 16;
        stW[1] = base + ((1 * 16 + wid) * 6) * 32 * 16 + lane * 16;
    }

    // ================= ENCODER (mma) =================
    float bR[2][2], bZ[2][2], bNi[2][2], bNh[2][2];
    #pragma unroll
    for (int ct = 0; ct < 2; ct++) {
        int jj = ct ? jB : jA;
        #pragma unroll
        for (int q = 0; q < 2; q++) {
            bR[ct][q]  = ebih[jj + q]          + ebhh[jj + q];
            bZ[ct][q]  = ebih[jj + q + HH]     + ebhh[jj + q + HH];
            bNi[ct][q] = ebih[jj + q + 2 * HH];
            bNh[ct][q] = ebhh[jj + q + 2 * HH];
        }
    }
    float hp[2][4];
    #pragma unroll
    for (int ct = 0; ct < 2; ct++) {
        int jj = ct ? jB : jA;
        #pragma unroll
        for (int pos = 0; pos < 4; pos++) {
            int b = r0l + ((pos >> 1) ? 8 : 0);
            hp[ct][pos] = h0[(size_t)(b0 + b) * HH + jj + (pos & 1)];
        }
    }
    #pragma unroll
    for (int ct = 0; ct < 2; ct++) {
        int jj = ct ? jB : jA;
        #pragma unroll
        for (int br = 0; br < 2; br++) {
            int b = r0l + br * 8;
            float v0 = hp[ct][br * 2 + 0], v1 = hp[ct][br * 2 + 1];
            *(unsigned*)&sm->abfH[b][FF + jj] = packhi(v0, v1);
            *(unsigned*)&sm->abfL[b][FF + jj] = packlo(v0, v1);
        }
    }
    {
        int i0 = tid * 2, bx = i0 >> 6, kx = i0 & 63;
        float2 xv = *(const float2*)&x[(size_t)(b0 + bx) * TT * FF + kx];
        *(unsigned*)&sm->abfH[bx][kx] = packhi(xv.x, xv.y);
        *(unsigned*)&sm->abfL[bx][kx] = packlo(xv.x, xv.y);
    }
    const unsigned aH = (unsigned)__cvta_generic_to_shared(&sm->abfH[0][0])
                      + (lane & 15) * (AROW * 2) + ((lane >> 4) * 8) * 2;
    const unsigned aL = (unsigned)__cvta_generic_to_shared(&sm->abfL[0][0])
                      + (lane & 15) * (AROW * 2) + ((lane >> 4) * 8) * 2;
    const uint4* eB = reinterpret_cast<const uint4*>(g_Bfrag)
                    + (size_t)wid * NJOBS * 32 + lane;
    const uint4* dB = reinterpret_cast<const uint4*>(g_BfragD)
                    + (size_t)wid * DJOBS * 32 + lane;
    const uint4* fB = reinterpret_cast<const uint4*>(g_BfragF)
                    + (size_t)wid * FJOBS * 32 + lane;
    __syncthreads();

    for (int t = 0; t < TT; t++) {
        float c0t[4] = {0, 0, 0, 0}, c1t[4] = {0, 0, 0, 0};
        float c2t[4] = {0, 0, 0, 0}, c3t[4] = {0, 0, 0, 0};
        float c4t[4] = {0, 0, 0, 0}, c5t[4] = {0, 0, 0, 0};
        float c6t[4] = {0, 0, 0, 0}, c7t[4] = {0, 0, 0, 0};

        // stage kt=0
        #pragma unroll
        for (int s = 0; s < 6; s++)
            CP16(stW[0] + s * 512, eB + s * 32);
        CP_COMMIT();

        #pragma unroll 2
        for (int kt = 0; kt < NKT; kt++) {
            if (kt + 1 < NKT) {
                const uint4* src = eB + (kt + 1) * 6 * 32;
                unsigned d = stW[(kt + 1) & 1];
                #pragma unroll
                for (int s = 0; s < 6; s++)
                    CP16(d + s * 512, src + s * 32);
                CP_COMMIT();
                CP_WAIT1();
            } else {
                CP_WAIT0();
            }
            unsigned ah0, ah1, ah2, ah3, al0, al1, al2, al3;
            LDSM4(ah0, ah1, ah2, ah3, aH + kt * 32);
            LDSM4(al0, al1, al2, al3, aL + kt * 32);
            const uint4* sp = &sm->bstage[kt & 1][wid][0][lane];
            uint4 bv;
            bv = sp[0];       MMA3(c0t, bv);
            bv = sp[32];      MMA3(c1t, bv);
            bv = sp[64];      MMA3(c2t, bv);
            bv = sp[96];      MMA3(c3t, bv);
            if (kt < 4) {
                bv = sp[128]; MMA3(c6t, bv);
                bv = sp[160]; MMA3(c7t, bv);
            } else {
                bv = sp[128]; MMA3(c4t, bv);
                bv = sp[160]; MMA3(c5t, bv);
            }
        }
        __syncthreads();

        #pragma unroll
        for (int ct = 0; ct < 2; ct++) {
            int jj = ct ? jB : jA;
            const float* cr = ct ? c1t : c0t;
            const float* cz = ct ? c3t : c2t;
            const float* ch = ct ? c5t : c4t;
            const float* ci = ct ? c7t : c6t;
            #pragma unroll
            for (int br = 0; br < 2; br++) {
                int b = r0l + br * 8;
                float hn[2];
                #pragma unroll
                for (int q = 0; q < 2; q++) {
                    int pos = br * 2 + q;
                    float rr = sigf(cr[pos] + bR[ct][q]);
                    float zz = sigf(cz[pos] + bZ[ct][q]);
                    float nn = tanh_f(ci[pos] + bNi[ct][q] + rr * (ch[pos] + bNh[ct][q]));
                    hn[q] = (1.f - zz) * nn + zz * hp[ct][pos];
                    hp[ct][pos] = hn[q];
                }
                *(unsigned*)&sm->abfH[b][FF + jj] = packhi(hn[0], hn[1]);
                *(unsigned*)&sm->abfL[b][FF + jj] = packlo(hn[0], hn[1]);
                size_t go = ((size_t)(b0 + b) * TT + t) * HH + jj;
                *(float2*)&g_hsf[go] = make_float2(hn[0], hn[1]);
                *(__half2*)&g_hs[go] = __floats2half2_rn(hn[0], hn[1]);
            }
        }
        if (t + 1 < TT) {
            int i0 = tid * 2, bx = i0 >> 6, kx = i0 & 63;
            float2 xv = *(const float2*)&x[((size_t)(b0 + bx) * TT + (t + 1)) * FF + kx];
            *(unsigned*)&sm->abfH[bx][kx] = packhi(xv.x, xv.y);
            *(unsigned*)&sm->abfL[bx][kx] = packlo(xv.x, xv.y);
        }
        __syncthreads();
    }

    // ---- A/C pass ----
    {
        int b = wid;
        float wq[8], bq[8];
        {
            float4 a0 = *(const float4*)&aWq[lane * 8];
            float4 a1 = *(const float4*)&aWq[lane * 8 + 4];
            float4 cc0 = *(const float4*)&abq[lane * 8];
            float4 cc1 = *(const float4*)&abq[lane * 8 + 4];
            wq[0]=a0.x; wq[1]=a0.y; wq[2]=a0.z; wq[3]=a0.w;
            wq[4]=a1.x; wq[5]=a1.y; wq[6]=a1.z; wq[7]=a1.w;
            bq[0]=cc0.x; bq[1]=cc0.y; bq[2]=cc0.z; bq[3]=cc0.w;
            bq[4]=cc1.x; bq[5]=cc1.y; bq[6]=cc1.z; bq[7]=cc1.w;
        }
        const float* hb = g_hsf + (size_t)(b0 + b) * TT * HH + lane * 8;
        for (int t = 0; t < TT; t++) {
            float4 h0v = *(const float4*)(hb + (size_t)t * HH);
            float4 h1v = *(const float4*)(hb + (size_t)t * HH + 4);
            float pa = wq[0]*h0v.x + wq[1]*h0v.y + wq[2]*h0v.z + wq[3]*h0v.w
                     + wq[4]*h1v.x + wq[5]*h1v.y + wq[6]*h1v.z + wq[7]*h1v.w;
            float pc = bq[0]*h0v.x + bq[1]*h0v.y + bq[2]*h0v.z + bq[3]*h0v.w
                     + bq[4]*h1v.x + bq[5]*h1v.y + bq[6]*h1v.z + bq[7]*h1v.w;
            #pragma unroll
            for (int off = 16; off; off >>= 1) {
                pa += __shfl_xor_sync(0xffffffffu, pa, off);
                pc += __shfl_xor_sync(0xffffffffu, pc, off);
            }
            if (lane == 0) { sm->A[b][t] = pa; sm->C[b][t] = pc; }
        }
    }

    // ======================= DECODER (mma) =======================
    float dR[2][2], dZ[2][2], dNi[2][2], dNh[2][2];
    float wiR[2][2], wiZ[2][2], wiN[2][2], f1bb[2][2], f2w[2][2];
    #pragma unroll
    for (int ct = 0; ct < 2; ct++) {
        int jj = ct ? jB : jA;
        #pragma unroll
        for (int q = 0; q < 2; q++) {
            dR[ct][q]   = dbih[jj + q]          + dbhh[jj + q];
            dZ[ct][q]   = dbih[jj + q + HH]     + dbhh[jj + q + HH];
            dNi[ct][q]  = dbih[jj + q + 2 * HH];
            dNh[ct][q]  = dbhh[jj + q + 2 * HH];
            wiR[ct][q]  = dWih[jj + q];
            wiZ[ct][q]  = dWih[jj + q + HH];
            wiN[ct][q]  = dWih[jj + q + 2 * HH];
            f1bb[ct][q] = f1b[jj + q];
            f2w[ct][q]  = f2W[jj + q];
        }
    }
    const float f2b0 = f2b[0];

    if (tid < BT)
        sm->prevs[tid] = x[((size_t)(b0 + tid) * TT + (TT - 1)) * FF];
    __syncthreads();

    const float scale = 0.0625f;
    for (int s = 0; s < OUTL; s++) {
        // ---- scores + softmax ----
        {
            int b = wid;
            float p = sm->prevs[b];
            float sc[4]; float mx = -1e30f;
            #pragma unroll
            for (int i = 0; i < 4; i++) {
                int tt2 = lane + 32 * i;
                sc[i] = (p * sm->A[b][tt2] + sm->C[b][tt2]) * scale;
                mx = fmaxf(mx, sc[i]);
            }
            #pragma unroll
            for (int off = 16; off; off >>= 1)
                mx = fmaxf(mx, __shfl_xor_sync(0xffffffffu, mx, off));
            float sum = 0.f;
            #pragma unroll
            for (int i = 0; i < 4; i++) { sc[i] = __expf(sc[i] - mx); sum += sc[i]; }
            #pragma unroll
            for (int off = 16; off; off >>= 1)
                sum += __shfl_xor_sync(0xffffffffu, sum, off);
            float inv = __fdividef(1.f, sum);
            #pragma unroll
            for (int i = 0; i < 4; i++) sm->ww[b][lane + 32 * i] = sc[i] * inv;
        }
        __syncthreads();

        // ---- ctx partials over 4 t-quarters (fp16 stream) ----
        {
            int th = tid >> 7, c = (tid & 127) * 2;
            float2 acc[BT];
            #pragma unroll
            for (int b = 0; b < BT; b++) acc[b] = make_float2(0.f, 0.f);
            const __half* base = g_hs + ((size_t)b0 * TT + th * 32) * HH + c;
            #pragma unroll 2
            for (int ti = 0; ti < 32; ti++) {
                int tt2 = th * 32 + ti;
                const __half* pb = base + (size_t)ti * HH;
                #pragma unroll
                for (int b = 0; b < BT; b++) {
                    float wv = sm->ww[b][tt2];
                    __half2 hv = *(const __half2*)(pb + (size_t)b * TT * HH);
                    float2 f = __half22float2(hv);
                    acc[b].x = fmaf(wv, f.x, acc[b].x);
                    acc[b].y = fmaf(wv, f.y, acc[b].y);
                }
            }
            #pragma unroll
            for (int b = 0; b < BT; b++)
                sm->ctxp[th][b][tid & 127] = __floats2half2_rn(acc[b].x, acc[b].y);
        }
        __syncthreads();

        // ---- combine: fp32 ctx tile + bf16 hi/lo A tile ----
        {
            int jp = tid & 127, bq4 = tid >> 7;
            int j2 = jp * 2;
            #pragma unroll
            for (int bb = 0; bb < 4; bb++) {
                int b = bq4 * 4 + bb;
                float2 p0 = __half22float2(sm->ctxp[0][b][jp]);
                float2 p1 = __half22float2(sm->ctxp[1][b][jp]);
                float2 p2 = __half22float2(sm->ctxp[2][b][jp]);
                float2 p3 = __half22float2(sm->ctxp[3][b][jp]);
                float v0 = p0.x + p1.x + p2.x + p3.x;
                float v1 = p0.y + p1.y + p2.y + p3.y;
                sm->ctxf[j2][b]     = v0;
                sm->ctxf[j2 + 1][b] = v1;
                *(unsigned*)&sm->abfH[b][FF + j2] = packhi(v0, v1);
                *(unsigned*)&sm->abfL[b][FF + j2] = packlo(v0, v1);
            }
        }
        __syncthreads();

        // ---- decoder GRU mma (staged) ----
        float cR0[4] = {0,0,0,0}, cR1[4] = {0,0,0,0};
        float cZ0[4] = {0,0,0,0}, cZ1[4] = {0,0,0,0};
        float cN0[4] = {0,0,0,0}, cN1[4] = {0,0,0,0};
        #pragma unroll
        for (int ss = 0; ss < 6; ss++)
            CP16(stW[0] + ss * 512, dB + ss * 32);
        CP_COMMIT();
        #pragma unroll 2
        for (int kt = 0; kt < 16; kt++) {
            if (kt + 1 < 16) {
                const uint4* src = dB + (kt + 1) * 6 * 32;
                unsigned d = stW[(kt + 1) & 1];
                #pragma unroll
                for (int ss = 0; ss < 6; ss++)
                    CP16(d + ss * 512, src + ss * 32);
                CP_COMMIT();
                CP_WAIT1();
            } else {
                CP_WAIT0();
            }
            unsigned ah0, ah1, ah2, ah3, al0, al1, al2, al3;
            LDSM4(ah0, ah1, ah2, ah3, aH + (kt + 4) * 32);
            LDSM4(al0, al1, al2, al3, aL + (kt + 4) * 32);
            const uint4* sp = &sm->bstage[kt & 1][wid][0][lane];
            uint4 bv;
            bv = sp[0];   MMA3(cR0, bv);
            bv = sp[32];  MMA3(cR1, bv);
            bv = sp[64];  MMA3(cZ0, bv);
            bv = sp[96];  MMA3(cZ1, bv);
            bv = sp[128]; MMA3(cN0, bv);
            bv = sp[160]; MMA3(cN1, bv);
        }
        __syncthreads();

        // ---- GRU epilogue: hd -> abf tile ----
        #pragma unroll
        for (int ct = 0; ct < 2; ct++) {
            int jj = ct ? jB : jA;
            const float* cr = ct ? cR1 : cR0;
            const float* cz = ct ? cZ1 : cZ0;
            const float* cn = ct ? cN1 : cN0;
            #pragma unroll
            for (int br = 0; br < 2; br++) {
                int b = r0l + br * 8;
                float pv = sm->prevs[b];
                float hd[2];
                #pragma unroll
                for (int q = 0; q < 2; q++) {
                    int pos = br * 2 + q;
                    float rr = sigf(cr[pos] + pv * wiR[ct][q] + dR[ct][q]);
                    float zz = sigf(cz[pos] + pv * wiZ[ct][q] + dZ[ct][q]);
                    float nn = tanh_f(pv * wiN[ct][q] + dNi[ct][q]
                                      + rr * (cn[pos] + dNh[ct][q]));
                    float cx = sm->ctxf[jj + q][b];
                    hd[q] = (1.f - zz) * nn + zz * cx;
                }
                *(unsigned*)&sm->abfH[b][FF + jj] = packhi(hd[0], hd[1]);
                *(unsigned*)&sm->abfL[b][FF + jj] = packlo(hd[0], hd[1]);
            }
        }
        __syncthreads();

        // ---- fc1 mma (staged) + relu + fc2 reduce ----
        {
            float cF0[4] = {0,0,0,0}, cF1[4] = {0,0,0,0};
            #pragma unroll
            for (int ss = 0; ss < 2; ss++)
                CP16(stW[0] + ss * 512, fB + ss * 32);
            CP_COMMIT();
            #pragma unroll 2
            for (int kt = 0; kt < 16; kt++) {
                if (kt + 1 < 16) {
                    const uint4* src = fB + (kt + 1) * 2 * 32;
                    unsigned d = stW[(kt + 1) & 1];
                    #pragma unroll
                    for (int ss = 0; ss < 2; ss++)
                        CP16(d + ss * 512, src + ss * 32);
                    CP_COMMIT();
                    CP_WAIT1();
                } else {
                    CP_WAIT0();
                }
                unsigned ah0, ah1, ah2, ah3, al0, al1, al2, al3;
                LDSM4(ah0, ah1, ah2, ah3, aH + (kt + 4) * 32);
                LDSM4(al0, al1, al2, al3, aL + (kt + 4) * 32);
                const uint4* sp = &sm->bstage[kt & 1][wid][0][lane];
                uint4 bv;
                bv = sp[0];  MMA3(cF0, bv);
                bv = sp[32]; MMA3(cF1, bv);
            }
            float s0 = 0.f, s1 = 0.f;
            #pragma unroll
            for (int ct = 0; ct < 2; ct++) {
                const float* cf = ct ? cF1 : cF0;
                #pragma unroll
                for (int q = 0; q < 2; q++) {
                    s0 += fmaxf(cf[q]     + f1bb[ct][q], 0.f) * f2w[ct][q];
                    s1 += fmaxf(cf[2 + q] + f1bb[ct][q], 0.f) * f2w[ct][q];
                }
            }
            s0 += __shfl_xor_sync(0xffffffffu, s0, 1);
            s0 += __shfl_xor_sync(0xffffffffu, s0, 2);
            s1 += __shfl_xor_sync(0xffffffffu, s1, 1);
            s1 += __shfl_xor_sync(0xffffffffu, s1, 2);
            if ((lane & 3) == 0) {
                sm->wpart[wid][r0l]     = s0;
                sm->wpart[wid][r0l + 8] = s1;
            }
        }
        __syncthreads();
        if (tid < BT) {
            float o = f2b0;
            #pragma unroll
            for (int w = 0; w < 16; w++) o += sm->wpart[w][tid];
            out[(size_t)(b0 + tid) * OUTL + s] = o;
            sm->prevs[tid] = o;
        }
        __syncthreads();
    }
}

extern "C" void kernel_launch(void* const* d_in, const int* in_sizes, int n_in,
                              void* d_out, int out_size) {
    const float* x    = (const float*)d_in[0];
    const float* h0   = (const float*)d_in[1];
    const float* eWih = (const float*)d_in[2];
    const float* eWhh = (const float*)d_in[3];
    const float* ebih = (const float*)d_in[4];
    const float* ebhh = (const float*)d_in[5];
    const float* dWih = (const float*)d_in[6];
    const float* dWhh = (const float*)d_in[7];
    const float* dbih = (const float*)d_in[8];
    const float* dbhh = (const float*)d_in[9];
    const float* aWq  = (const float*)d_in[10];
    const float* abq  = (const float*)d_in[11];
    const float* f1W  = (const float*)d_in[12];
    const float* f1b  = (const float*)d_in[13];
    const float* f2W  = (const float*)d_in[14];
    const float* f2b  = (const float*)d_in[15];
    float* out = (float*)d_out;

    prep_frag <<<(16 * NJOBS * 32 + 255) / 256, 256>>>(eWih, eWhh);
    prep_fragD<<<(16 * DJOBS * 32 + 255) / 256, 256>>>(dWhh);
    prep_fragF<<<(16 * FJOBS * 32 + 255) / 256, 256>>>(f1W);

    size_t shmem = sizeof(SM);
    cudaFuncSetAttribute(forecaster_kernel,
                         cudaFuncAttributeMaxDynamicSharedMemorySize, (int)shmem);
    forecaster_kernel<<<NCTA, NTHR, shmem>>>(
        x, h0, ebih, ebhh, dWih, dbih, dbhh, aWq, abq, f1b, f2W, f2b, out);
}